// round 10
// baseline (speedup 1.0000x reference)
#include <cuda_runtime.h>
#include <cstdint>
#include <math.h>

#define BB 4
#define SS 2048
#define DD 1024

#define TM 128
#define TN 64
#define TK 32
#define NTHREADS 256
#define STAGES 3
#define STAGE_BYTES 24576            // A fp32 16K | B fp32 8K
#define DSM_BYTES (STAGES * STAGE_BYTES + 1024)

// ---------------------------------------------------------------------------
// Scratch (__device__ globals: allocation-guard-safe). All values stored as
// fp32 whose mantissas are pre-rounded to tf32 (RNA) by their producers.
// ---------------------------------------------------------------------------
__device__ float g_X [(size_t)BB * SS * DD];          // x (tf32)      32 MB
__device__ float g_Wt[3][(size_t)DD * DD];            // W^T (tf32)    12 MB
__device__ float g_Q [(size_t)BB * SS * DD];          // Q (tf32)      32 MB
__device__ float g_K [(size_t)BB * SS * DD];          // K (tf32)      32 MB
__device__ float g_V [(size_t)BB * SS * DD];          // V fp32        32 MB
__device__ float g_Vt[(size_t)BB * SS * DD];          // V^T (tf32)    32 MB
__device__ float g_S [(size_t)BB * SS * SS];          // scores fp32   64 MB
__device__ float g_P [(size_t)BB * SS * SS];          // probs (tf32)  64 MB

// ---------------------------------------------------------------------------
// Helpers
// ---------------------------------------------------------------------------
__device__ __forceinline__ uint32_t smem_u32(const void* p) {
    uint32_t a;
    asm("{ .reg .u64 t; cvta.to.shared.u64 t, %1; cvt.u32.u64 %0, t; }"
        : "=r"(a) : "l"(p));
    return a;
}

__device__ __forceinline__ uint32_t tf32r(float f) {
    uint32_t r;
    asm("cvt.rna.tf32.f32 %0, %1;" : "=r"(r) : "f"(f));
    return r;
}

#define LDSM4(r, a)                                                        \
    asm volatile("ldmatrix.sync.aligned.m8n8.x4.shared.b16 "               \
                 "{%0,%1,%2,%3}, [%4];"                                    \
                 : "=r"((r)[0]), "=r"((r)[1]), "=r"((r)[2]), "=r"((r)[3])  \
                 : "r"(a))

#define MMATF32(d, a, b0, b1)                                              \
    asm volatile("mma.sync.aligned.m16n8k8.row.col.f32.tf32.tf32.f32 "     \
                 "{%0,%1,%2,%3},{%4,%5,%6,%7},{%8,%9},{%0,%1,%2,%3};"      \
                 : "+f"((d)[0]), "+f"((d)[1]), "+f"((d)[2]), "+f"((d)[3])  \
                 : "r"((a)[0]), "r"((a)[1]), "r"((a)[2]), "r"((a)[3]),     \
                   "r"(b0), "r"(b1))

#define CPA16(dst, src)                                                    \
    asm volatile("cp.async.cg.shared.global [%0], [%1], 16;"               \
                 :: "r"(dst), "l"(src))
#define CPA_COMMIT()  asm volatile("cp.async.commit_group;" ::: "memory")
#define CPA_WAIT1()   asm volatile("cp.async.wait_group 1;" ::: "memory")

// ===========================================================================
// Shared GEMM body (CTA 128x64, 3-stage cp.async, warp tile 32x32).
// Fragments double-buffered: kblk+1's LDSMs issue while kblk's MMAs run,
// and the first kblk's LDSMs issue BEFORE the next stage's cp.async burst.
// ===========================================================================
struct GemmCtx {
    uint32_t sbase;
    uint32_t aoffs;
    const float* gA;
    const float* gB;
    long long a32, b32;
    uint32_t aSw[2], bSw[2];
    uint32_t hb;
};

__device__ __forceinline__ void gemm_setup(GemmCtx& cx, uint32_t sbase,
                                           const float* A, int lda, int m0,
                                           const float* B, int ldb, int n0,
                                           int tid, int lane, int wid)
{
    cx.sbase = sbase;
    const int wm = (wid & 3) * 32;
    const int wn = (wid >> 2) * 32;

    const int arow = tid >> 3, cu = tid & 7;
    cx.aoffs = ((uint32_t)arow * 128u + (uint32_t)cu * 16u)
               ^ (((uint32_t)(arow & 7)) << 4);
    cx.gA = A + (long long)(m0 + arow) * lda + cu * 4;
    cx.gB = B + (long long)(n0 + arow) * ldb + cu * 4;
    cx.a32 = (long long)32 * lda;
    cx.b32 = (long long)32 * ldb;

    const int fr = lane & 15;
    cx.hb = (uint32_t)(lane >> 4) * 16u;
#pragma unroll
    for (int mf = 0; mf < 2; mf++) {
        int row = wm + 16 * mf + fr;
        cx.aSw[mf] = (uint32_t)row * 128u ^ (((uint32_t)(row & 7)) << 4);
    }
#pragma unroll
    for (int g = 0; g < 2; g++) {
        int row = wn + 16 * g + fr;
        cx.bSw[g] = 16384u + ((uint32_t)row * 128u ^ (((uint32_t)(row & 7)) << 4));
    }
}

__device__ __forceinline__ void gemm_issue(const GemmCtx& cx, int sidx, int k0)
{
    const uint32_t sb_ = cx.sbase + (uint32_t)sidx * STAGE_BYTES;
    CPA16(sb_ + cx.aoffs,          cx.gA + k0);
    CPA16(sb_ + cx.aoffs +  4096u, cx.gA + k0 + cx.a32);
    CPA16(sb_ + cx.aoffs +  8192u, cx.gA + k0 + 2 * cx.a32);
    CPA16(sb_ + cx.aoffs + 12288u, cx.gA + k0 + 3 * cx.a32);
    CPA16(sb_ + 16384u + cx.aoffs,         cx.gB + k0);
    CPA16(sb_ + 16384u + cx.aoffs + 4096u, cx.gB + k0 + cx.b32);
}

#define FRAG_LOAD(fb, kblk_)                                               \
    do {                                                                   \
        const uint32_t kc_ = (uint32_t)((kblk_) * 32) + cx.hb;             \
        LDSM4(af[fb][0], buf + (cx.aSw[0] ^ kc_));                         \
        LDSM4(af[fb][1], buf + (cx.aSw[1] ^ kc_));                         \
        LDSM4(bf[fb][0], buf + (cx.bSw[0] ^ kc_));                         \
        LDSM4(bf[fb][1], buf + (cx.bSw[1] ^ kc_));                         \
    } while (0)

__device__ __forceinline__ void gemm_mainloop(const GemmCtx& cx, int KB,
                                              float acc[2][4][4])
{
#pragma unroll
    for (int s = 0; s < STAGES - 1; s++) {
        if (s < KB) gemm_issue(cx, s, s * TK);
        CPA_COMMIT();
    }

    int sidx_c = 0;
    int sidx_w = STAGES - 1;
    for (int kb = 0; kb < KB; kb++) {
        CPA_WAIT1();
        __syncthreads();

        const uint32_t buf = cx.sbase + (uint32_t)sidx_c * STAGE_BYTES;
        if (++sidx_c == STAGES) sidx_c = 0;

        uint32_t af[2][2][4], bf[2][2][4];
        // critical path first: fragments for kblk 0
        FRAG_LOAD(0, 0);

        // then the next stage's global->smem burst
        if (kb + STAGES - 1 < KB)
            gemm_issue(cx, sidx_w, (kb + STAGES - 1) * TK);
        CPA_COMMIT();
        if (++sidx_w == STAGES) sidx_w = 0;

#pragma unroll
        for (int kblk = 0; kblk < 4; kblk++) {            // 4 x k8 per k-block
            const int cur = kblk & 1;
            if (kblk < 3) {
                const int nxt = cur ^ 1;
                FRAG_LOAD(nxt, kblk + 1);
            }
#pragma unroll
            for (int mf = 0; mf < 2; mf++)
#pragma unroll
                for (int g = 0; g < 2; g++)
#pragma unroll
                    for (int s = 0; s < 2; s++)
                        MMATF32(acc[mf][2 * g + s], af[cur][mf],
                                bf[cur][g][s], bf[cur][g][s + 2]);
        }
    }
}

// ---------------------------------------------------------------------------
// Generic GEMM kernel (scores / P@V).  C[m,n] = alpha * sum_k A[m,k]*B[n,k].
//   TRI : skip tiles fully above the diagonal; PERQ: K limit = (by+1)*TM.
//   Both variants reverse blockIdx.y so expensive tile-rows schedule FIRST.
// ---------------------------------------------------------------------------
template<bool TRI, bool PERQ>
__global__ void __launch_bounds__(NTHREADS, 3)
mma_gemm(const float* __restrict__ A, int lda, long long sA,
         const float* __restrict__ B, int ldb, long long sB,
         float* __restrict__ C, int ldc, long long sC,
         int Kfull, float alpha)
{
    const int by = (TRI || PERQ) ? (gridDim.y - 1 - blockIdx.y) : blockIdx.y;
    const int m0 = by * TM;
    const int n0 = blockIdx.x * TN;
    if (TRI && n0 > m0 + TM - 1) return;

    extern __shared__ char dsm[];
    const uint32_t sbase = (smem_u32(dsm) + 1023u) & ~1023u;

    const long long z = blockIdx.z;
    A += sA * z; B += sB * z;

    const int Klim = PERQ ? (by + 1) * TM : Kfull;
    const int KB = Klim / TK;

    const int tid  = threadIdx.x;
    const int lane = tid & 31;
    const int wid  = tid >> 5;

    GemmCtx cx;
    gemm_setup(cx, sbase, A, lda, m0, B, ldb, n0, tid, lane, wid);

    float acc[2][4][4];
#pragma unroll
    for (int mf = 0; mf < 2; mf++)
#pragma unroll
        for (int nf = 0; nf < 4; nf++)
#pragma unroll
            for (int j = 0; j < 4; j++) acc[mf][nf][j] = 0.0f;

    gemm_mainloop(cx, KB, acc);

    // epilogue
    const int wm = (wid & 3) * 32;
    const int wn = (wid >> 2) * 32;
    const int gq = lane >> 2, t = lane & 3;
    C += sC * z;
#pragma unroll
    for (int mf = 0; mf < 2; mf++) {
#pragma unroll
        for (int nf = 0; nf < 4; nf++) {
            const int r0  = m0 + wm + 16 * mf + gq;
            const int col = n0 + wn + 8 * nf + 2 * t;
            float2 o0, o1;
            o0.x = acc[mf][nf][0] * alpha;
            o0.y = acc[mf][nf][1] * alpha;
            o1.x = acc[mf][nf][2] * alpha;
            o1.y = acc[mf][nf][3] * alpha;
            *reinterpret_cast<float2*>(C + (long long)r0 * ldc + col)       = o0;
            *reinterpret_cast<float2*>(C + (long long)(r0 + 8) * ldc + col) = o1;
        }
    }
}

// ---------------------------------------------------------------------------
// Fused QKV kernel: blockIdx.z in 0..2 selects {Wq,Wk,Wv} and {Q,K,V}.
// Q,K outputs rounded to tf32 (they feed later MMAs); V kept fp32.
// ---------------------------------------------------------------------------
__global__ void __launch_bounds__(NTHREADS, 3)
qkv_gemm(const float* __restrict__ X, const float* __restrict__ Wt,
         float* __restrict__ Qo, float* __restrict__ Ko, float* __restrict__ Vo)
{
    const int m0 = blockIdx.y * TM;
    const int n0 = blockIdx.x * TN;
    const int z  = blockIdx.z;

    extern __shared__ char dsm[];
    const uint32_t sbase = (smem_u32(dsm) + 1023u) & ~1023u;

    const float* B = Wt + (size_t)z * DD * DD;
    float* C = (z == 0) ? Qo : (z == 1) ? Ko : Vo;
    const bool roundOut = (z < 2);

    const int tid  = threadIdx.x;
    const int lane = tid & 31;
    const int wid  = tid >> 5;

    GemmCtx cx;
    gemm_setup(cx, sbase, X, DD, m0, B, DD, n0, tid, lane, wid);

    float acc[2][4][4];
#pragma unroll
    for (int mf = 0; mf < 2; mf++)
#pragma unroll
        for (int nf = 0; nf < 4; nf++)
#pragma unroll
            for (int j = 0; j < 4; j++) acc[mf][nf][j] = 0.0f;

    gemm_mainloop(cx, DD / TK, acc);

    const int wm = (wid & 3) * 32;
    const int wn = (wid >> 2) * 32;
    const int gq = lane >> 2, t = lane & 3;
#pragma unroll
    for (int mf = 0; mf < 2; mf++) {
#pragma unroll
        for (int nf = 0; nf < 4; nf++) {
            const int r0  = m0 + wm + 16 * mf + gq;
            const int col = n0 + wn + 8 * nf + 2 * t;
            float v0 = acc[mf][nf][0];
            float v1 = acc[mf][nf][1];
            float v2 = acc[mf][nf][2];
            float v3 = acc[mf][nf][3];
            if (roundOut) {
                v0 = __uint_as_float(tf32r(v0));
                v1 = __uint_as_float(tf32r(v1));
                v2 = __uint_as_float(tf32r(v2));
                v3 = __uint_as_float(tf32r(v3));
            }
            float2 o0, o1;
            o0.x = v0; o0.y = v1; o1.x = v2; o1.y = v3;
            *reinterpret_cast<float2*>(C + (long long)r0 * DD + col)       = o0;
            *reinterpret_cast<float2*>(C + (long long)(r0 + 8) * DD + col) = o1;
        }
    }
}

// ---------------------------------------------------------------------------
// fp32 -> tf32-rounded fp32 elementwise (vectorized x4)
// ---------------------------------------------------------------------------
__global__ void __launch_bounds__(256)
convert_tf32(const float* __restrict__ in, float* __restrict__ out, int n4)
{
    int i = blockIdx.x * 256 + threadIdx.x;
    if (i >= n4) return;
    float4 v = reinterpret_cast<const float4*>(in)[i];
    v.x = __uint_as_float(tf32r(v.x));
    v.y = __uint_as_float(tf32r(v.y));
    v.z = __uint_as_float(tf32r(v.z));
    v.w = __uint_as_float(tf32r(v.w));
    reinterpret_cast<float4*>(out)[i] = v;
}

// ---------------------------------------------------------------------------
// fp32 [R x C] -> transposed tf32-rounded fp32 [C x R] (per-z batch)
// ---------------------------------------------------------------------------
__global__ void __launch_bounds__(256)
transpose_tf32(const float* __restrict__ in, float* __restrict__ out,
               int R, int C, long long sIn, long long sOut)
{
    __shared__ float t[32][33];
    in  += sIn * blockIdx.z;
    out += sOut * blockIdx.z;
    const int c0 = blockIdx.x * 32, r0 = blockIdx.y * 32;
#pragma unroll
    for (int j = threadIdx.y; j < 32; j += 8)
        t[j][threadIdx.x] = in[(long long)(r0 + j) * C + c0 + threadIdx.x];
    __syncthreads();
#pragma unroll
    for (int j = threadIdx.y; j < 32; j += 8)
        out[(long long)(c0 + j) * R + r0 + threadIdx.x] =
            __uint_as_float(tf32r(t[threadIdx.x][j]));
}

// ---------------------------------------------------------------------------
// Causal row softmax: fp32 scores -> tf32-rounded probs; zero-fill to the
// 128-aligned block end so P@V needs no masking.
// ---------------------------------------------------------------------------
__global__ void __launch_bounds__(256)
softmax_causal(const float* __restrict__ S, float* __restrict__ P)
{
    const int row = blockIdx.x;          // b*S + q
    const int q   = row & (SS - 1);
    const int limit = ((q >> 7) + 1) << 7;
    const float* p = S + (long long)row * SS;
    float* po = P + (long long)row * SS;

    const int tid = threadIdx.x;
    float v[8];
    float mx = -INFINITY;
#pragma unroll
    for (int i = 0; i < 8; i++) {
        int idx = i * 256 + tid;
        v[i] = (idx <= q) ? p[idx] : -INFINITY;
        mx = fmaxf(mx, v[i]);
    }

    __shared__ float red[256];
    red[tid] = mx;
    __syncthreads();
#pragma unroll
    for (int s = 128; s > 0; s >>= 1) {
        if (tid < s) red[tid] = fmaxf(red[tid], red[tid + s]);
        __syncthreads();
    }
    mx = red[0];
    __syncthreads();

    float e[8];
    float sum = 0.0f;
#pragma unroll
    for (int i = 0; i < 8; i++) {
        e[i] = __expf(v[i] - mx);
        sum += e[i];
    }
    red[tid] = sum;
    __syncthreads();
#pragma unroll
    for (int s = 128; s > 0; s >>= 1) {
        if (tid < s) red[tid] += red[tid + s];
        __syncthreads();
    }
    const float inv = 1.0f / red[0];

#pragma unroll
    for (int i = 0; i < 8; i++) {
        int idx = i * 256 + tid;
        if (idx <= q)          po[idx] = __uint_as_float(tf32r(e[i] * inv));
        else if (idx < limit)  po[idx] = 0.0f;
    }
}

// ---------------------------------------------------------------------------
// Launch sequence (graph-capturable: kernel launches only).
// NOTE: scores GEMM is deliberately launch index 5 so ncu's "-s 5 -c 1"
// captures a GEMM instead of a transpose. Vt transpose moved after it
// (Vt is only consumed by the P@V kernel).
// ---------------------------------------------------------------------------
extern "C" void kernel_launch(void* const* d_in, const int* in_sizes, int n_in,
                              void* d_out, int out_size)
{
    const float* x  = (const float*)d_in[0];
    const float* Wq = (const float*)d_in[1];
    const float* Wk = (const float*)d_in[2];
    const float* Wv = (const float*)d_in[3];
    float* out = (float*)d_out;

    float *X, *Wt, *Q, *K, *V, *Vt, *Sb, *P;
    cudaGetSymbolAddress((void**)&X,  g_X);
    cudaGetSymbolAddress((void**)&Wt, g_Wt);
    cudaGetSymbolAddress((void**)&Q,  g_Q);
    cudaGetSymbolAddress((void**)&K,  g_K);
    cudaGetSymbolAddress((void**)&V,  g_V);
    cudaGetSymbolAddress((void**)&Vt, g_Vt);
    cudaGetSymbolAddress((void**)&Sb, g_S);
    cudaGetSymbolAddress((void**)&P,  g_P);

    const size_t wsz = (size_t)DD * DD;
    float *Wt0 = Wt, *Wt1 = Wt + wsz, *Wt2 = Wt + 2 * wsz;

    cudaFuncSetAttribute(qkv_gemm,
                         cudaFuncAttributeMaxDynamicSharedMemorySize, DSM_BYTES);
    cudaFuncSetAttribute(mma_gemm<true, false>,
                         cudaFuncAttributeMaxDynamicSharedMemorySize, DSM_BYTES);
    cudaFuncSetAttribute(mma_gemm<false, true>,
                         cudaFuncAttributeMaxDynamicSharedMemorySize, DSM_BYTES);

    const long long sQKV = (long long)SS * DD;
    const long long sSco = (long long)SS * SS;
    const float scale = 0.03125f;     // 1024^-0.5

    dim3 tb(32, 8);

    // idx 0) round x to tf32
    const int xn4 = BB * SS * DD / 4;
    convert_tf32<<<(xn4 + 255) / 256, 256>>>(x, X, xn4);
    // idx 1-3) W^T (K-major, tf32)
    transpose_tf32<<<dim3(DD / 32, DD / 32, 1), tb>>>(Wq, Wt0, DD, DD, 0, 0);
    transpose_tf32<<<dim3(DD / 32, DD / 32, 1), tb>>>(Wk, Wt1, DD, DD, 0, 0);
    transpose_tf32<<<dim3(DD / 32, DD / 32, 1), tb>>>(Wv, Wt2, DD, DD, 0, 0);

    // idx 4) Fused QKV projection: one launch, z selects W / output
    dim3 gq(DD / TN, (BB * SS) / TM, 3);
    qkv_gemm<<<gq, NTHREADS, DSM_BYTES>>>(X, Wt, Q, K, V);

    // idx 5) scores = scale * Q @ K^T  (ncu capture target)
    dim3 gs(SS / TN, SS / TM, BB);
    mma_gemm<true, false><<<gs, NTHREADS, DSM_BYTES>>>(
        Q, DD, sQKV, K, DD, sQKV, Sb, SS, sSco, DD, scale);

    // idx 6) V^T per batch (rounds to tf32): [2048,1024] -> [1024,2048]
    transpose_tf32<<<dim3(DD / 32, SS / 32, BB), tb>>>(V, Vt, SS, DD, sQKV, sQKV);

    // idx 7) causal softmax -> tf32 probs (+ zero-fill to 128 boundary)
    softmax_causal<<<BB * SS, 256>>>(Sb, P);

    // idx 8) out = P @ V  (per-q-tile K range; heavy rows first)
    dim3 gp(DD / TN, SS / TM, BB);
    mma_gemm<false, true><<<gp, NTHREADS, DSM_BYTES>>>(
        P, SS, sSco, Vt, SS, sQKV, out, DD, sQKV, 0, 1.0f);
}

// round 11
// speedup vs baseline: 1.0593x; 1.0593x over previous
#include <cuda_runtime.h>
#include <cstdint>
#include <math.h>

#define BB 4
#define SS 2048
#define DD 1024

#define TM 128
#define TN 64
#define TK 32
#define NTHREADS 256
#define STAGES 3
#define STAGE_BYTES 24576            // A fp32 16K | B fp32 8K
#define DSM_BYTES (STAGES * STAGE_BYTES + 1024)

// ---------------------------------------------------------------------------
// Scratch (__device__ globals: allocation-guard-safe). All values stored as
// fp32 whose mantissas are pre-rounded to tf32 (RNA) by their producers.
// ---------------------------------------------------------------------------
__device__ float g_X [(size_t)BB * SS * DD];          // x (tf32)      32 MB
__device__ float g_Wt[3][(size_t)DD * DD];            // W^T (tf32)    12 MB
__device__ float g_Q [(size_t)BB * SS * DD];          // Q (tf32)      32 MB
__device__ float g_K [(size_t)BB * SS * DD];          // K (tf32)      32 MB
__device__ float g_V [(size_t)BB * SS * DD];          // V fp32        32 MB
__device__ float g_Vt[(size_t)BB * SS * DD];          // V^T (tf32)    32 MB
__device__ float g_S [(size_t)BB * SS * SS];          // scores fp32   64 MB
__device__ float g_P [(size_t)BB * SS * SS];          // probs (tf32)  64 MB

// ---------------------------------------------------------------------------
// Helpers
// ---------------------------------------------------------------------------
__device__ __forceinline__ uint32_t smem_u32(const void* p) {
    uint32_t a;
    asm("{ .reg .u64 t; cvta.to.shared.u64 t, %1; cvt.u32.u64 %0, t; }"
        : "=r"(a) : "l"(p));
    return a;
}

__device__ __forceinline__ uint32_t tf32r(float f) {
    uint32_t r;
    asm("cvt.rna.tf32.f32 %0, %1;" : "=r"(r) : "f"(f));
    return r;
}

#define LDSM4(r, a)                                                        \
    asm volatile("ldmatrix.sync.aligned.m8n8.x4.shared.b16 "               \
                 "{%0,%1,%2,%3}, [%4];"                                    \
                 : "=r"((r)[0]), "=r"((r)[1]), "=r"((r)[2]), "=r"((r)[3])  \
                 : "r"(a))

#define MMATF32(d, a, b0, b1)                                              \
    asm volatile("mma.sync.aligned.m16n8k8.row.col.f32.tf32.tf32.f32 "     \
                 "{%0,%1,%2,%3},{%4,%5,%6,%7},{%8,%9},{%0,%1,%2,%3};"      \
                 : "+f"((d)[0]), "+f"((d)[1]), "+f"((d)[2]), "+f"((d)[3])  \
                 : "r"((a)[0]), "r"((a)[1]), "r"((a)[2]), "r"((a)[3]),     \
                   "r"(b0), "r"(b1))

#define CPA16(dst, src)                                                    \
    asm volatile("cp.async.cg.shared.global [%0], [%1], 16;"               \
                 :: "r"(dst), "l"(src))
#define CPA_COMMIT()  asm volatile("cp.async.commit_group;" ::: "memory")
#define CPA_WAIT1()   asm volatile("cp.async.wait_group 1;" ::: "memory")

// ===========================================================================
// Shared GEMM body (CTA 128x64, 3-stage cp.async, warp tile 32x32).
// Single-buffered fragments (R9-proven: fits the 84-reg/thread budget that
// 3 CTAs/SM requires; double-buffering spills and regresses).
// ===========================================================================
struct GemmCtx {
    uint32_t sbase;
    uint32_t aoffs;
    const float* gA;
    const float* gB;
    long long a32, b32;
    uint32_t aSw[2], bSw[2];
    uint32_t hb;
};

__device__ __forceinline__ void gemm_setup(GemmCtx& cx, uint32_t sbase,
                                           const float* A, int lda, int m0,
                                           const float* B, int ldb, int n0,
                                           int tid, int lane, int wid)
{
    cx.sbase = sbase;
    const int wm = (wid & 3) * 32;
    const int wn = (wid >> 2) * 32;

    const int arow = tid >> 3, cu = tid & 7;
    cx.aoffs = ((uint32_t)arow * 128u + (uint32_t)cu * 16u)
               ^ (((uint32_t)(arow & 7)) << 4);
    cx.gA = A + (long long)(m0 + arow) * lda + cu * 4;
    cx.gB = B + (long long)(n0 + arow) * ldb + cu * 4;
    cx.a32 = (long long)32 * lda;
    cx.b32 = (long long)32 * ldb;

    const int fr = lane & 15;
    cx.hb = (uint32_t)(lane >> 4) * 16u;
#pragma unroll
    for (int mf = 0; mf < 2; mf++) {
        int row = wm + 16 * mf + fr;
        cx.aSw[mf] = (uint32_t)row * 128u ^ (((uint32_t)(row & 7)) << 4);
    }
#pragma unroll
    for (int g = 0; g < 2; g++) {
        int row = wn + 16 * g + fr;
        cx.bSw[g] = 16384u + ((uint32_t)row * 128u ^ (((uint32_t)(row & 7)) << 4));
    }
}

__device__ __forceinline__ void gemm_issue(const GemmCtx& cx, int sidx, int k0)
{
    const uint32_t sb_ = cx.sbase + (uint32_t)sidx * STAGE_BYTES;
    CPA16(sb_ + cx.aoffs,          cx.gA + k0);
    CPA16(sb_ + cx.aoffs +  4096u, cx.gA + k0 + cx.a32);
    CPA16(sb_ + cx.aoffs +  8192u, cx.gA + k0 + 2 * cx.a32);
    CPA16(sb_ + cx.aoffs + 12288u, cx.gA + k0 + 3 * cx.a32);
    CPA16(sb_ + 16384u + cx.aoffs,         cx.gB + k0);
    CPA16(sb_ + 16384u + cx.aoffs + 4096u, cx.gB + k0 + cx.b32);
}

__device__ __forceinline__ void gemm_mainloop(const GemmCtx& cx, int KB,
                                              float acc[2][4][4])
{
#pragma unroll
    for (int s = 0; s < STAGES - 1; s++) {
        if (s < KB) gemm_issue(cx, s, s * TK);
        CPA_COMMIT();
    }

    int sidx_c = 0;
    int sidx_w = STAGES - 1;
    for (int kb = 0; kb < KB; kb++) {
        CPA_WAIT1();
        __syncthreads();

        if (kb + STAGES - 1 < KB)
            gemm_issue(cx, sidx_w, (kb + STAGES - 1) * TK);
        CPA_COMMIT();
        if (++sidx_w == STAGES) sidx_w = 0;

        const uint32_t buf = cx.sbase + (uint32_t)sidx_c * STAGE_BYTES;
        if (++sidx_c == STAGES) sidx_c = 0;

#pragma unroll
        for (int kblk = 0; kblk < 4; kblk++) {            // 4 x k8 per k-block
            const uint32_t kc = (uint32_t)(kblk * 32) + cx.hb;
            uint32_t a[2][4], b[2][4];
            LDSM4(a[0], buf + (cx.aSw[0] ^ kc));
            LDSM4(a[1], buf + (cx.aSw[1] ^ kc));
            LDSM4(b[0], buf + (cx.bSw[0] ^ kc));
            LDSM4(b[1], buf + (cx.bSw[1] ^ kc));
#pragma unroll
            for (int mf = 0; mf < 2; mf++)
#pragma unroll
                for (int g = 0; g < 2; g++)
#pragma unroll
                    for (int s = 0; s < 2; s++)
                        MMATF32(acc[mf][2 * g + s], a[mf], b[g][s], b[g][s + 2]);
        }
    }
}

// ---------------------------------------------------------------------------
// Generic GEMM kernel (scores / P@V).  C[m,n] = alpha * sum_k A[m,k]*B[n,k].
//   TRI : skip tiles fully above the diagonal; PERQ: K limit = (by+1)*TM.
//   Both variants reverse blockIdx.y so expensive tile-rows schedule FIRST.
// ---------------------------------------------------------------------------
template<bool TRI, bool PERQ>
__global__ void __launch_bounds__(NTHREADS, 3)
mma_gemm(const float* __restrict__ A, int lda, long long sA,
         const float* __restrict__ B, int ldb, long long sB,
         float* __restrict__ C, int ldc, long long sC,
         int Kfull, float alpha)
{
    const int by = (TRI || PERQ) ? (gridDim.y - 1 - blockIdx.y) : blockIdx.y;
    const int m0 = by * TM;
    const int n0 = blockIdx.x * TN;
    if (TRI && n0 > m0 + TM - 1) return;

    extern __shared__ char dsm[];
    const uint32_t sbase = (smem_u32(dsm) + 1023u) & ~1023u;

    const long long z = blockIdx.z;
    A += sA * z; B += sB * z;

    const int Klim = PERQ ? (by + 1) * TM : Kfull;
    const int KB = Klim / TK;

    const int tid  = threadIdx.x;
    const int lane = tid & 31;
    const int wid  = tid >> 5;

    GemmCtx cx;
    gemm_setup(cx, sbase, A, lda, m0, B, ldb, n0, tid, lane, wid);

    float acc[2][4][4];
#pragma unroll
    for (int mf = 0; mf < 2; mf++)
#pragma unroll
        for (int nf = 0; nf < 4; nf++)
#pragma unroll
            for (int j = 0; j < 4; j++) acc[mf][nf][j] = 0.0f;

    gemm_mainloop(cx, KB, acc);

    // epilogue
    const int wm = (wid & 3) * 32;
    const int wn = (wid >> 2) * 32;
    const int gq = lane >> 2, t = lane & 3;
    C += sC * z;
#pragma unroll
    for (int mf = 0; mf < 2; mf++) {
#pragma unroll
        for (int nf = 0; nf < 4; nf++) {
            const int r0  = m0 + wm + 16 * mf + gq;
            const int col = n0 + wn + 8 * nf + 2 * t;
            float2 o0, o1;
            o0.x = acc[mf][nf][0] * alpha;
            o0.y = acc[mf][nf][1] * alpha;
            o1.x = acc[mf][nf][2] * alpha;
            o1.y = acc[mf][nf][3] * alpha;
            *reinterpret_cast<float2*>(C + (long long)r0 * ldc + col)       = o0;
            *reinterpret_cast<float2*>(C + (long long)(r0 + 8) * ldc + col) = o1;
        }
    }
}

// ---------------------------------------------------------------------------
// Fused QKV kernel: blockIdx.z in 0..2 selects {Wq,Wk,Wv} and {Q,K,V}.
// Q,K outputs rounded to tf32 (they feed later MMAs); V kept fp32.
// ---------------------------------------------------------------------------
__global__ void __launch_bounds__(NTHREADS, 3)
qkv_gemm(const float* __restrict__ X, const float* __restrict__ Wt,
         float* __restrict__ Qo, float* __restrict__ Ko, float* __restrict__ Vo)
{
    const int m0 = blockIdx.y * TM;
    const int n0 = blockIdx.x * TN;
    const int z  = blockIdx.z;

    extern __shared__ char dsm[];
    const uint32_t sbase = (smem_u32(dsm) + 1023u) & ~1023u;

    const float* B = Wt + (size_t)z * DD * DD;
    float* C = (z == 0) ? Qo : (z == 1) ? Ko : Vo;
    const bool roundOut = (z < 2);

    const int tid  = threadIdx.x;
    const int lane = tid & 31;
    const int wid  = tid >> 5;

    GemmCtx cx;
    gemm_setup(cx, sbase, X, DD, m0, B, DD, n0, tid, lane, wid);

    float acc[2][4][4];
#pragma unroll
    for (int mf = 0; mf < 2; mf++)
#pragma unroll
        for (int nf = 0; nf < 4; nf++)
#pragma unroll
            for (int j = 0; j < 4; j++) acc[mf][nf][j] = 0.0f;

    gemm_mainloop(cx, DD / TK, acc);

    const int wm = (wid & 3) * 32;
    const int wn = (wid >> 2) * 32;
    const int gq = lane >> 2, t = lane & 3;
#pragma unroll
    for (int mf = 0; mf < 2; mf++) {
#pragma unroll
        for (int nf = 0; nf < 4; nf++) {
            const int r0  = m0 + wm + 16 * mf + gq;
            const int col = n0 + wn + 8 * nf + 2 * t;
            float v0 = acc[mf][nf][0];
            float v1 = acc[mf][nf][1];
            float v2 = acc[mf][nf][2];
            float v3 = acc[mf][nf][3];
            if (roundOut) {
                v0 = __uint_as_float(tf32r(v0));
                v1 = __uint_as_float(tf32r(v1));
                v2 = __uint_as_float(tf32r(v2));
                v3 = __uint_as_float(tf32r(v3));
            }
            float2 o0, o1;
            o0.x = v0; o0.y = v1; o1.x = v2; o1.y = v3;
            *reinterpret_cast<float2*>(C + (long long)r0 * DD + col)       = o0;
            *reinterpret_cast<float2*>(C + (long long)(r0 + 8) * DD + col) = o1;
        }
    }
}

// ---------------------------------------------------------------------------
// fp32 -> tf32-rounded fp32 elementwise (vectorized x4)
// ---------------------------------------------------------------------------
__global__ void __launch_bounds__(256)
convert_tf32(const float* __restrict__ in, float* __restrict__ out, int n4)
{
    int i = blockIdx.x * 256 + threadIdx.x;
    if (i >= n4) return;
    float4 v = reinterpret_cast<const float4*>(in)[i];
    v.x = __uint_as_float(tf32r(v.x));
    v.y = __uint_as_float(tf32r(v.y));
    v.z = __uint_as_float(tf32r(v.z));
    v.w = __uint_as_float(tf32r(v.w));
    reinterpret_cast<float4*>(out)[i] = v;
}

// ---------------------------------------------------------------------------
// Merged W^T transpose: one launch, blockIdx.z in 0..2 selects Wq/Wk/Wv.
// fp32 [DD x DD] -> transposed tf32-rounded fp32 [DD x DD].
// ---------------------------------------------------------------------------
__global__ void __launch_bounds__(256)
transpose_w3(const float* __restrict__ Wq, const float* __restrict__ Wk,
             const float* __restrict__ Wv, float* __restrict__ WtBase)
{
    __shared__ float t[32][33];
    const int z = blockIdx.z;
    const float* in = (z == 0) ? Wq : (z == 1) ? Wk : Wv;
    float* out = WtBase + (size_t)z * DD * DD;
    const int c0 = blockIdx.x * 32, r0 = blockIdx.y * 32;
#pragma unroll
    for (int j = threadIdx.y; j < 32; j += 8)
        t[j][threadIdx.x] = in[(long long)(r0 + j) * DD + c0 + threadIdx.x];
    __syncthreads();
#pragma unroll
    for (int j = threadIdx.y; j < 32; j += 8)
        out[(long long)(c0 + j) * DD + r0 + threadIdx.x] =
            __uint_as_float(tf32r(t[threadIdx.x][j]));
}

// ---------------------------------------------------------------------------
// fp32 [R x C] -> transposed tf32-rounded fp32 [C x R] (per-z batch; for Vt)
// ---------------------------------------------------------------------------
__global__ void __launch_bounds__(256)
transpose_tf32(const float* __restrict__ in, float* __restrict__ out,
               int R, int C, long long sIn, long long sOut)
{
    __shared__ float t[32][33];
    in  += sIn * blockIdx.z;
    out += sOut * blockIdx.z;
    const int c0 = blockIdx.x * 32, r0 = blockIdx.y * 32;
#pragma unroll
    for (int j = threadIdx.y; j < 32; j += 8)
        t[j][threadIdx.x] = in[(long long)(r0 + j) * C + c0 + threadIdx.x];
    __syncthreads();
#pragma unroll
    for (int j = threadIdx.y; j < 32; j += 8)
        out[(long long)(c0 + j) * R + r0 + threadIdx.x] =
            __uint_as_float(tf32r(t[threadIdx.x][j]));
}

// ---------------------------------------------------------------------------
// Causal row softmax: fp32 scores -> tf32-rounded probs; zero-fill to the
// 128-aligned block end so P@V needs no masking. Warp-shuffle reductions
// (2 barriers per block instead of 18).
// ---------------------------------------------------------------------------
__global__ void __launch_bounds__(256)
softmax_causal(const float* __restrict__ S, float* __restrict__ P)
{
    const int row = blockIdx.x;          // b*S + q
    const int q   = row & (SS - 1);
    const int limit = ((q >> 7) + 1) << 7;
    const float* p = S + (long long)row * SS;
    float* po = P + (long long)row * SS;

    const int tid  = threadIdx.x;
    const int lane = tid & 31;
    const int wrp  = tid >> 5;

    float v[8];
    float mx = -INFINITY;
#pragma unroll
    for (int i = 0; i < 8; i++) {
        int idx = i * 256 + tid;
        v[i] = (idx <= q) ? p[idx] : -INFINITY;
        mx = fmaxf(mx, v[i]);
    }

    __shared__ float wmax[8], wsum[8];
#pragma unroll
    for (int o = 16; o > 0; o >>= 1)
        mx = fmaxf(mx, __shfl_xor_sync(0xFFFFFFFFu, mx, o));
    if (lane == 0) wmax[wrp] = mx;
    __syncthreads();
    mx = wmax[0];
#pragma unroll
    for (int w = 1; w < 8; w++) mx = fmaxf(mx, wmax[w]);

    float e[8];
    float sum = 0.0f;
#pragma unroll
    for (int i = 0; i < 8; i++) {
        e[i] = __expf(v[i] - mx);
        sum += e[i];
    }
#pragma unroll
    for (int o = 16; o > 0; o >>= 1)
        sum += __shfl_xor_sync(0xFFFFFFFFu, sum, o);
    if (lane == 0) wsum[wrp] = sum;
    __syncthreads();
    sum = wsum[0];
#pragma unroll
    for (int w = 1; w < 8; w++) sum += wsum[w];
    const float inv = 1.0f / sum;

#pragma unroll
    for (int i = 0; i < 8; i++) {
        int idx = i * 256 + tid;
        if (idx <= q)          po[idx] = __uint_as_float(tf32r(e[i] * inv));
        else if (idx < limit)  po[idx] = 0.0f;
    }
}

// ---------------------------------------------------------------------------
// Launch sequence (graph-capturable: kernel launches only).
// Order: convert(0), W^T merged(1), QKV(2), scores(3), Vt(4), softmax(5),
// P@V(6). The scores GEMM at index 3 targets ncu's capture window assuming
// ~2 harness-prepended launches (last round -s 5 landed on our index ~3).
// ---------------------------------------------------------------------------
extern "C" void kernel_launch(void* const* d_in, const int* in_sizes, int n_in,
                              void* d_out, int out_size)
{
    const float* x  = (const float*)d_in[0];
    const float* Wq = (const float*)d_in[1];
    const float* Wk = (const float*)d_in[2];
    const float* Wv = (const float*)d_in[3];
    float* out = (float*)d_out;

    float *X, *Wt, *Q, *K, *V, *Vt, *Sb, *P;
    cudaGetSymbolAddress((void**)&X,  g_X);
    cudaGetSymbolAddress((void**)&Wt, g_Wt);
    cudaGetSymbolAddress((void**)&Q,  g_Q);
    cudaGetSymbolAddress((void**)&K,  g_K);
    cudaGetSymbolAddress((void**)&V,  g_V);
    cudaGetSymbolAddress((void**)&Vt, g_Vt);
    cudaGetSymbolAddress((void**)&Sb, g_S);
    cudaGetSymbolAddress((void**)&P,  g_P);

    cudaFuncSetAttribute(qkv_gemm,
                         cudaFuncAttributeMaxDynamicSharedMemorySize, DSM_BYTES);
    cudaFuncSetAttribute(mma_gemm<true, false>,
                         cudaFuncAttributeMaxDynamicSharedMemorySize, DSM_BYTES);
    cudaFuncSetAttribute(mma_gemm<false, true>,
                         cudaFuncAttributeMaxDynamicSharedMemorySize, DSM_BYTES);

    const long long sQKV = (long long)SS * DD;
    const long long sSco = (long long)SS * SS;
    const float scale = 0.03125f;     // 1024^-0.5

    dim3 tb(32, 8);

    // idx 0) round x to tf32
    const int xn4 = BB * SS * DD / 4;
    convert_tf32<<<(xn4 + 255) / 256, 256>>>(x, X, xn4);

    // idx 1) W^T merged (K-major, tf32), z selects Wq/Wk/Wv
    transpose_w3<<<dim3(DD / 32, DD / 32, 3), tb>>>(Wq, Wk, Wv, Wt);

    // idx 2) Fused QKV projection: one launch, z selects W / output
    dim3 gq(DD / TN, (BB * SS) / TM, 3);
    qkv_gemm<<<gq, NTHREADS, DSM_BYTES>>>(X, Wt, Q, K, V);

    // idx 3) scores = scale * Q @ K^T  (ncu capture target)
    dim3 gs(SS / TN, SS / TM, BB);
    mma_gemm<true, false><<<gs, NTHREADS, DSM_BYTES>>>(
        Q, DD, sQKV, K, DD, sQKV, Sb, SS, sSco, DD, scale);

    // idx 4) V^T per batch (rounds to tf32): [2048,1024] -> [1024,2048]
    transpose_tf32<<<dim3(DD / 32, SS / 32, BB), tb>>>(V, Vt, SS, DD, sQKV, sQKV);

    // idx 5) causal softmax -> tf32 probs (+ zero-fill to 128 boundary)
    softmax_causal<<<BB * SS, 256>>>(Sb, P);

    // idx 6) out = P @ V  (per-q-tile K range; heavy rows first)
    dim3 gp(DD / TN, SS / TM, BB);
    mma_gemm<false, true><<<gp, NTHREADS, DSM_BYTES>>>(
        P, SS, sSco, Vt, SS, sQKV, out, DD, sQKV, 0, 1.0f);
}

// round 12
// speedup vs baseline: 1.0949x; 1.0336x over previous
#include <cuda_runtime.h>
#include <cstdint>
#include <math.h>

#define BB 4
#define SS 2048
#define DD 1024

#define TM 128
#define TN 64
#define TK 32
#define NTHREADS 256
#define STAGES 3
#define STAGE_BYTES 24576            // A fp32 16K | B fp32 8K
#define DSM_BYTES (STAGES * STAGE_BYTES + 1024)

// ---------------------------------------------------------------------------
// Scratch (__device__ globals). Values pre-rounded to tf32 by producers.
// ---------------------------------------------------------------------------
__device__ float g_X [(size_t)BB * SS * DD];          // x (tf32)      32 MB
__device__ float g_Wt[3][(size_t)DD * DD];            // W^T (tf32)    12 MB
__device__ float g_Q [(size_t)BB * SS * DD];          // Q (tf32)      32 MB
__device__ float g_K [(size_t)BB * SS * DD];          // K (tf32)      32 MB
__device__ float g_Vt[(size_t)BB * SS * DD];          // V^T (tf32)    32 MB
__device__ float g_S [(size_t)BB * SS * SS];          // scores fp32   64 MB
__device__ float g_P [(size_t)BB * SS * SS];          // probs (tf32)  64 MB

// ---------------------------------------------------------------------------
// Helpers
// ---------------------------------------------------------------------------
__device__ __forceinline__ uint32_t smem_u32(const void* p) {
    uint32_t a;
    asm("{ .reg .u64 t; cvta.to.shared.u64 t, %1; cvt.u32.u64 %0, t; }"
        : "=r"(a) : "l"(p));
    return a;
}

__device__ __forceinline__ uint32_t tf32r(float f) {
    uint32_t r;
    asm("cvt.rna.tf32.f32 %0, %1;" : "=r"(r) : "f"(f));
    return r;
}

#define LDSM4(r, a)                                                        \
    asm volatile("ldmatrix.sync.aligned.m8n8.x4.shared.b16 "               \
                 "{%0,%1,%2,%3}, [%4];"                                    \
                 : "=r"((r)[0]), "=r"((r)[1]), "=r"((r)[2]), "=r"((r)[3])  \
                 : "r"(a))

#define MMATF32(d, a, b0, b1)                                              \
    asm volatile("mma.sync.aligned.m16n8k8.row.col.f32.tf32.tf32.f32 "     \
                 "{%0,%1,%2,%3},{%4,%5,%6,%7},{%8,%9},{%0,%1,%2,%3};"      \
                 : "+f"((d)[0]), "+f"((d)[1]), "+f"((d)[2]), "+f"((d)[3])  \
                 : "r"((a)[0]), "r"((a)[1]), "r"((a)[2]), "r"((a)[3]),     \
                   "r"(b0), "r"(b1))

#define CPA16(dst, src)                                                    \
    asm volatile("cp.async.cg.shared.global [%0], [%1], 16;"               \
                 :: "r"(dst), "l"(src))
#define CPA_COMMIT()  asm volatile("cp.async.commit_group;" ::: "memory")
#define CPA_WAIT1()   asm volatile("cp.async.wait_group 1;" ::: "memory")

// ===========================================================================
// Shared GEMM body (CTA 128x64, 3-stage cp.async, warp tile 32x32).
// Single-buffered fragments (84-reg budget for 3 CTAs/SM). The next-stage
// cp.async burst issues AFTER kblk0's fragments+MMAs (critical path first).
// ===========================================================================
struct GemmCtx {
    uint32_t sbase;
    uint32_t aoffs;
    const float* gA;
    const float* gB;
    long long a32, b32;
    uint32_t aSw[2], bSw[2];
    uint32_t hb;
};

__device__ __forceinline__ void gemm_setup(GemmCtx& cx, uint32_t sbase,
                                           const float* A, int lda, int m0,
                                           const float* B, int ldb, int n0,
                                           int tid, int lane, int wid)
{
    cx.sbase = sbase;
    const int wm = (wid & 3) * 32;
    const int wn = (wid >> 2) * 32;

    const int arow = tid >> 3, cu = tid & 7;
    cx.aoffs = ((uint32_t)arow * 128u + (uint32_t)cu * 16u)
               ^ (((uint32_t)(arow & 7)) << 4);
    cx.gA = A + (long long)(m0 + arow) * lda + cu * 4;
    cx.gB = B + (long long)(n0 + arow) * ldb + cu * 4;
    cx.a32 = (long long)32 * lda;
    cx.b32 = (long long)32 * ldb;

    const int fr = lane & 15;
    cx.hb = (uint32_t)(lane >> 4) * 16u;
#pragma unroll
    for (int mf = 0; mf < 2; mf++) {
        int row = wm + 16 * mf + fr;
        cx.aSw[mf] = (uint32_t)row * 128u ^ (((uint32_t)(row & 7)) << 4);
    }
#pragma unroll
    for (int g = 0; g < 2; g++) {
        int row = wn + 16 * g + fr;
        cx.bSw[g] = 16384u + ((uint32_t)row * 128u ^ (((uint32_t)(row & 7)) << 4));
    }
}

__device__ __forceinline__ void gemm_issue(const GemmCtx& cx, int sidx, int k0)
{
    const uint32_t sb_ = cx.sbase + (uint32_t)sidx * STAGE_BYTES;
    CPA16(sb_ + cx.aoffs,          cx.gA + k0);
    CPA16(sb_ + cx.aoffs +  4096u, cx.gA + k0 + cx.a32);
    CPA16(sb_ + cx.aoffs +  8192u, cx.gA + k0 + 2 * cx.a32);
    CPA16(sb_ + cx.aoffs + 12288u, cx.gA + k0 + 3 * cx.a32);
    CPA16(sb_ + 16384u + cx.aoffs,         cx.gB + k0);
    CPA16(sb_ + 16384u + cx.aoffs + 4096u, cx.gB + k0 + cx.b32);
}

__device__ __forceinline__ void gemm_mainloop(const GemmCtx& cx, int KB,
                                              float acc[2][4][4])
{
#pragma unroll
    for (int s = 0; s < STAGES - 1; s++) {
        if (s < KB) gemm_issue(cx, s, s * TK);
        CPA_COMMIT();
    }

    int sidx_c = 0;
    int sidx_w = STAGES - 1;
    for (int kb = 0; kb < KB; kb++) {
        CPA_WAIT1();
        __syncthreads();

        const uint32_t buf = cx.sbase + (uint32_t)sidx_c * STAGE_BYTES;
        if (++sidx_c == STAGES) sidx_c = 0;

#pragma unroll
        for (int kblk = 0; kblk < 4; kblk++) {            // 4 x k8 per k-block
            const uint32_t kc = (uint32_t)(kblk * 32) + cx.hb;
            uint32_t a[2][4], b[2][4];
            LDSM4(a[0], buf + (cx.aSw[0] ^ kc));
            LDSM4(a[1], buf + (cx.aSw[1] ^ kc));
            LDSM4(b[0], buf + (cx.bSw[0] ^ kc));
            LDSM4(b[1], buf + (cx.bSw[1] ^ kc));
#pragma unroll
            for (int mf = 0; mf < 2; mf++)
#pragma unroll
                for (int g = 0; g < 2; g++)
#pragma unroll
                    for (int s = 0; s < 2; s++)
                        MMATF32(acc[mf][2 * g + s], a[mf], b[g][s], b[g][s + 2]);

            // issue the next stage AFTER the first k8's critical path
            if (kblk == 0) {
                if (kb + STAGES - 1 < KB)
                    gemm_issue(cx, sidx_w, (kb + STAGES - 1) * TK);
                CPA_COMMIT();
                if (++sidx_w == STAGES) sidx_w = 0;
            }
        }
    }
}

// ---------------------------------------------------------------------------
// Generic GEMM kernel (scores / P@V).  C[m,n] = alpha * sum_k A[m,k]*B[n,k].
//   TRI : skip tiles fully above the diagonal; PERQ: K limit = (by+1)*TM.
//   Both variants reverse blockIdx.y so expensive tile-rows schedule FIRST.
// ---------------------------------------------------------------------------
template<bool TRI, bool PERQ>
__global__ void __launch_bounds__(NTHREADS, 3)
mma_gemm(const float* __restrict__ A, int lda, long long sA,
         const float* __restrict__ B, int ldb, long long sB,
         float* __restrict__ C, int ldc, long long sC,
         int Kfull, float alpha)
{
    const int by = (TRI || PERQ) ? (gridDim.y - 1 - blockIdx.y) : blockIdx.y;
    const int m0 = by * TM;
    const int n0 = blockIdx.x * TN;
    if (TRI && n0 > m0 + TM - 1) return;

    extern __shared__ char dsm[];
    const uint32_t sbase = (smem_u32(dsm) + 1023u) & ~1023u;

    const long long z = blockIdx.z;
    A += sA * z; B += sB * z;

    const int Klim = PERQ ? (by + 1) * TM : Kfull;
    const int KB = Klim / TK;

    const int tid  = threadIdx.x;
    const int lane = tid & 31;
    const int wid  = tid >> 5;

    GemmCtx cx;
    gemm_setup(cx, sbase, A, lda, m0, B, ldb, n0, tid, lane, wid);

    float acc[2][4][4];
#pragma unroll
    for (int mf = 0; mf < 2; mf++)
#pragma unroll
        for (int nf = 0; nf < 4; nf++)
#pragma unroll
            for (int j = 0; j < 4; j++) acc[mf][nf][j] = 0.0f;

    gemm_mainloop(cx, KB, acc);

    // epilogue
    const int wm = (wid & 3) * 32;
    const int wn = (wid >> 2) * 32;
    const int gq = lane >> 2, t = lane & 3;
    C += sC * z;
#pragma unroll
    for (int mf = 0; mf < 2; mf++) {
#pragma unroll
        for (int nf = 0; nf < 4; nf++) {
            const int r0  = m0 + wm + 16 * mf + gq;
            const int col = n0 + wn + 8 * nf + 2 * t;
            float2 o0, o1;
            o0.x = acc[mf][nf][0] * alpha;
            o0.y = acc[mf][nf][1] * alpha;
            o1.x = acc[mf][nf][2] * alpha;
            o1.y = acc[mf][nf][3] * alpha;
            *reinterpret_cast<float2*>(C + (long long)r0 * ldc + col)       = o0;
            *reinterpret_cast<float2*>(C + (long long)(r0 + 8) * ldc + col) = o1;
        }
    }
}

// ---------------------------------------------------------------------------
// Fused QKV kernel: blockIdx.z in 0..2 selects {Wq,Wk,Wv}.
//   z=0/1: Q/K written tf32-rounded, row-major.
//   z=2  : V written DIRECTLY TRANSPOSED (per-batch [DD][SS]) + tf32-rounded,
//          via an SMEM-staged transpose in the epilogue (no separate kernel).
// ---------------------------------------------------------------------------
__global__ void __launch_bounds__(NTHREADS, 3)
qkv_gemm(const float* __restrict__ X, const float* __restrict__ Wt,
         float* __restrict__ Qo, float* __restrict__ Ko, float* __restrict__ VtO)
{
    const int m0 = blockIdx.y * TM;
    const int n0 = blockIdx.x * TN;
    const int z  = blockIdx.z;

    extern __shared__ char dsm[];
    const uint32_t sbase = (smem_u32(dsm) + 1023u) & ~1023u;

    const float* B = Wt + (size_t)z * DD * DD;

    const int tid  = threadIdx.x;
    const int lane = tid & 31;
    const int wid  = tid >> 5;

    GemmCtx cx;
    gemm_setup(cx, sbase, X, DD, m0, B, DD, n0, tid, lane, wid);

    float acc[2][4][4];
#pragma unroll
    for (int mf = 0; mf < 2; mf++)
#pragma unroll
        for (int nf = 0; nf < 4; nf++)
#pragma unroll
            for (int j = 0; j < 4; j++) acc[mf][nf][j] = 0.0f;

    gemm_mainloop(cx, DD / TK, acc);

    const int wm = (wid & 3) * 32;
    const int wn = (wid >> 2) * 32;
    const int gq = lane >> 2, t = lane & 3;

    if (z < 2) {
        float* C = (z == 0) ? Qo : Ko;
#pragma unroll
        for (int mf = 0; mf < 2; mf++) {
#pragma unroll
            for (int nf = 0; nf < 4; nf++) {
                const int r0  = m0 + wm + 16 * mf + gq;
                const int col = n0 + wn + 8 * nf + 2 * t;
                float2 o0, o1;
                o0.x = __uint_as_float(tf32r(acc[mf][nf][0]));
                o0.y = __uint_as_float(tf32r(acc[mf][nf][1]));
                o1.x = __uint_as_float(tf32r(acc[mf][nf][2]));
                o1.y = __uint_as_float(tf32r(acc[mf][nf][3]));
                *reinterpret_cast<float2*>(C + (long long)r0 * DD + col)       = o0;
                *reinterpret_cast<float2*>(C + (long long)(r0 + 8) * DD + col) = o1;
            }
        }
    } else {
        // ---- transposed V epilogue ----
        __syncthreads();                       // pipeline smem now free
        float* ts = reinterpret_cast<float*>(dsm +
                        (size_t)(sbase - smem_u32(dsm)));   // aligned base
        // stage acc as ts[n][m], row pitch 132 floats (conflict-free stores)
#pragma unroll
        for (int mf = 0; mf < 2; mf++) {
#pragma unroll
            for (int nf = 0; nf < 4; nf++) {
                const int m_ = wm + 16 * mf + gq;
                const int n_ = wn + 8 * nf + 2 * t;
                ts[n_ * 132 + m_]             = acc[mf][nf][0];
                ts[(n_ + 1) * 132 + m_]       = acc[mf][nf][1];
                ts[n_ * 132 + m_ + 8]         = acc[mf][nf][2];
                ts[(n_ + 1) * 132 + m_ + 8]   = acc[mf][nf][3];
            }
        }
        __syncthreads();
        // write out: thread -> (row n = tid>>2, chunk c = tid&3), 8 float4
        const int vr = tid >> 2;
        const int vc = tid & 3;
        const int b  = m0 >> 11;               // batch (S = 2048)
        const int s0 = m0 & (SS - 1);
        float* dst = VtO + (size_t)b * SS * DD
                   + (size_t)(n0 + vr) * SS + s0 + vc * 32;
#pragma unroll
        for (int i = 0; i < 8; i++) {
            float4 v = *reinterpret_cast<const float4*>(
                ts + vr * 132 + vc * 32 + i * 4);
            v.x = __uint_as_float(tf32r(v.x));
            v.y = __uint_as_float(tf32r(v.y));
            v.z = __uint_as_float(tf32r(v.z));
            v.w = __uint_as_float(tf32r(v.w));
            *reinterpret_cast<float4*>(dst + i * 4) = v;
        }
    }
}

// ---------------------------------------------------------------------------
// fp32 -> tf32-rounded fp32 elementwise (vectorized x4)
// ---------------------------------------------------------------------------
__global__ void __launch_bounds__(256)
convert_tf32(const float* __restrict__ in, float* __restrict__ out, int n4)
{
    int i = blockIdx.x * 256 + threadIdx.x;
    if (i >= n4) return;
    float4 v = reinterpret_cast<const float4*>(in)[i];
    v.x = __uint_as_float(tf32r(v.x));
    v.y = __uint_as_float(tf32r(v.y));
    v.z = __uint_as_float(tf32r(v.z));
    v.w = __uint_as_float(tf32r(v.w));
    reinterpret_cast<float4*>(out)[i] = v;
}

// ---------------------------------------------------------------------------
// Merged W^T transpose: one launch, blockIdx.z in 0..2 selects Wq/Wk/Wv.
// ---------------------------------------------------------------------------
__global__ void __launch_bounds__(256)
transpose_w3(const float* __restrict__ Wq, const float* __restrict__ Wk,
             const float* __restrict__ Wv, float* __restrict__ WtBase)
{
    __shared__ float t[32][33];
    const int z = blockIdx.z;
    const float* in = (z == 0) ? Wq : (z == 1) ? Wk : Wv;
    float* out = WtBase + (size_t)z * DD * DD;
    const int c0 = blockIdx.x * 32, r0 = blockIdx.y * 32;
#pragma unroll
    for (int j = threadIdx.y; j < 32; j += 8)
        t[j][threadIdx.x] = in[(long long)(r0 + j) * DD + c0 + threadIdx.x];
    __syncthreads();
#pragma unroll
    for (int j = threadIdx.y; j < 32; j += 8)
        out[(long long)(c0 + j) * DD + r0 + threadIdx.x] =
            __uint_as_float(tf32r(t[threadIdx.x][j]));
}

// ---------------------------------------------------------------------------
// Causal row softmax: fp32 scores -> tf32-rounded probs; zero-fill to the
// 128-aligned block end so P@V needs no masking. Warp-shuffle reductions.
// ---------------------------------------------------------------------------
__global__ void __launch_bounds__(256)
softmax_causal(const float* __restrict__ S, float* __restrict__ P)
{
    const int row = blockIdx.x;          // b*S + q
    const int q   = row & (SS - 1);
    const int limit = ((q >> 7) + 1) << 7;
    const float* p = S + (long long)row * SS;
    float* po = P + (long long)row * SS;

    const int tid  = threadIdx.x;
    const int lane = tid & 31;
    const int wrp  = tid >> 5;

    float v[8];
    float mx = -INFINITY;
#pragma unroll
    for (int i = 0; i < 8; i++) {
        int idx = i * 256 + tid;
        v[i] = (idx <= q) ? p[idx] : -INFINITY;
        mx = fmaxf(mx, v[i]);
    }

    __shared__ float wmax[8], wsum[8];
#pragma unroll
    for (int o = 16; o > 0; o >>= 1)
        mx = fmaxf(mx, __shfl_xor_sync(0xFFFFFFFFu, mx, o));
    if (lane == 0) wmax[wrp] = mx;
    __syncthreads();
    mx = wmax[0];
#pragma unroll
    for (int w = 1; w < 8; w++) mx = fmaxf(mx, wmax[w]);

    float e[8];
    float sum = 0.0f;
#pragma unroll
    for (int i = 0; i < 8; i++) {
        e[i] = __expf(v[i] - mx);
        sum += e[i];
    }
#pragma unroll
    for (int o = 16; o > 0; o >>= 1)
        sum += __shfl_xor_sync(0xFFFFFFFFu, sum, o);
    if (lane == 0) wsum[wrp] = sum;
    __syncthreads();
    sum = wsum[0];
#pragma unroll
    for (int w = 1; w < 8; w++) sum += wsum[w];
    const float inv = 1.0f / sum;

#pragma unroll
    for (int i = 0; i < 8; i++) {
        int idx = i * 256 + tid;
        if (idx <= q)          po[idx] = __uint_as_float(tf32r(e[i] * inv));
        else if (idx < limit)  po[idx] = 0.0f;
    }
}

// ---------------------------------------------------------------------------
// Launch sequence (graph-capturable: kernel launches only).
// Order: convert(0), W^T merged(1), QKV+Vt(2), scores(3), softmax(4), P@V(5).
// ---------------------------------------------------------------------------
extern "C" void kernel_launch(void* const* d_in, const int* in_sizes, int n_in,
                              void* d_out, int out_size)
{
    const float* x  = (const float*)d_in[0];
    const float* Wq = (const float*)d_in[1];
    const float* Wk = (const float*)d_in[2];
    const float* Wv = (const float*)d_in[3];
    float* out = (float*)d_out;

    float *X, *Wt, *Q, *K, *Vt, *Sb, *P;
    cudaGetSymbolAddress((void**)&X,  g_X);
    cudaGetSymbolAddress((void**)&Wt, g_Wt);
    cudaGetSymbolAddress((void**)&Q,  g_Q);
    cudaGetSymbolAddress((void**)&K,  g_K);
    cudaGetSymbolAddress((void**)&Vt, g_Vt);
    cudaGetSymbolAddress((void**)&Sb, g_S);
    cudaGetSymbolAddress((void**)&P,  g_P);

    cudaFuncSetAttribute(qkv_gemm,
                         cudaFuncAttributeMaxDynamicSharedMemorySize, DSM_BYTES);
    cudaFuncSetAttribute(mma_gemm<true, false>,
                         cudaFuncAttributeMaxDynamicSharedMemorySize, DSM_BYTES);
    cudaFuncSetAttribute(mma_gemm<false, true>,
                         cudaFuncAttributeMaxDynamicSharedMemorySize, DSM_BYTES);

    const long long sQKV = (long long)SS * DD;
    const long long sSco = (long long)SS * SS;
    const float scale = 0.03125f;     // 1024^-0.5

    dim3 tb(32, 8);

    // idx 0) round x to tf32
    const int xn4 = BB * SS * DD / 4;
    convert_tf32<<<(xn4 + 255) / 256, 256>>>(x, X, xn4);

    // idx 1) W^T merged (K-major, tf32), z selects Wq/Wk/Wv
    transpose_w3<<<dim3(DD / 32, DD / 32, 3), tb>>>(Wq, Wk, Wv, Wt);

    // idx 2) Fused QKV projection; V emitted transposed (per-batch [DD][SS])
    dim3 gq(DD / TN, (BB * SS) / TM, 3);
    qkv_gemm<<<gq, NTHREADS, DSM_BYTES>>>(X, Wt, Q, K, Vt);

    // idx 3) scores = scale * Q @ K^T  (ncu capture target)
    dim3 gs(SS / TN, SS / TM, BB);
    mma_gemm<true, false><<<gs, NTHREADS, DSM_BYTES>>>(
        Q, DD, sQKV, K, DD, sQKV, Sb, SS, sSco, DD, scale);

    // idx 4) causal softmax -> tf32 probs (+ zero-fill to 128 boundary)
    softmax_causal<<<BB * SS, 256>>>(Sb, P);

    // idx 5) out = P @ V  (per-q-tile K range; heavy rows first)
    dim3 gp(DD / TN, SS / TM, BB);
    mma_gemm<false, true><<<gp, NTHREADS, DSM_BYTES>>>(
        P, SS, sSco, Vt, SS, sQKV, out, DD, sQKV, 0, 1.0f);
}

// round 13
// speedup vs baseline: 1.1180x; 1.0211x over previous
#include <cuda_runtime.h>
#include <cstdint>
#include <math.h>

#define BB 4
#define SS 2048
#define DD 1024

#define TM 128
#define TN 64
#define TK 32
#define NTHREADS 256
#define STAGES 3
#define STAGE_BYTES 24576            // A fp32 16K | B fp32 8K
#define DSM_BYTES (STAGES * STAGE_BYTES + 1024)

// ---------------------------------------------------------------------------
// Scratch (__device__ globals; zero-initialized at module load — the partial-
// sum buffer relies on this: dead slots are never written and read as 0).
// ---------------------------------------------------------------------------
__device__ float g_X [(size_t)BB * SS * DD];          // x (tf32)      32 MB
__device__ float g_Wt[3][(size_t)DD * DD];            // W^T (tf32)    12 MB
__device__ float g_Q [(size_t)BB * SS * DD];          // Q (tf32)      32 MB
__device__ float g_K [(size_t)BB * SS * DD];          // K (tf32)      32 MB
__device__ float g_Vt[(size_t)BB * SS * DD];          // V^T (tf32)    32 MB
__device__ float g_P [(size_t)BB * SS * SS];          // exp-scores     64 MB
__device__ float g_PS[(size_t)BB * SS * 64];          // row partials    2 MB
__device__ float g_RI[(size_t)BB * SS];               // 1/rowsum       32 KB

// ---------------------------------------------------------------------------
// Helpers
// ---------------------------------------------------------------------------
__device__ __forceinline__ uint32_t smem_u32(const void* p) {
    uint32_t a;
    asm("{ .reg .u64 t; cvta.to.shared.u64 t, %1; cvt.u32.u64 %0, t; }"
        : "=r"(a) : "l"(p));
    return a;
}

__device__ __forceinline__ uint32_t tf32r(float f) {
    uint32_t r;
    asm("cvt.rna.tf32.f32 %0, %1;" : "=r"(r) : "f"(f));
    return r;
}

#define LDSM4(r, a)                                                        \
    asm volatile("ldmatrix.sync.aligned.m8n8.x4.shared.b16 "               \
                 "{%0,%1,%2,%3}, [%4];"                                    \
                 : "=r"((r)[0]), "=r"((r)[1]), "=r"((r)[2]), "=r"((r)[3])  \
                 : "r"(a))

#define MMATF32(d, a, b0, b1)                                              \
    asm volatile("mma.sync.aligned.m16n8k8.row.col.f32.tf32.tf32.f32 "     \
                 "{%0,%1,%2,%3},{%4,%5,%6,%7},{%8,%9},{%0,%1,%2,%3};"      \
                 : "+f"((d)[0]), "+f"((d)[1]), "+f"((d)[2]), "+f"((d)[3])  \
                 : "r"((a)[0]), "r"((a)[1]), "r"((a)[2]), "r"((a)[3]),     \
                   "r"(b0), "r"(b1))

#define CPA16(dst, src)                                                    \
    asm volatile("cp.async.cg.shared.global [%0], [%1], 16;"               \
                 :: "r"(dst), "l"(src))
#define CPA_COMMIT()  asm volatile("cp.async.commit_group;" ::: "memory")
#define CPA_WAIT1()   asm volatile("cp.async.wait_group 1;" ::: "memory")

// ===========================================================================
// Shared GEMM body (CTA 128x64, 3-stage cp.async, warp tile 32x32).
// ===========================================================================
struct GemmCtx {
    uint32_t sbase;
    uint32_t aoffs;
    const float* gA;
    const float* gB;
    long long a32, b32;
    uint32_t aSw[2], bSw[2];
    uint32_t hb;
};

__device__ __forceinline__ void gemm_setup(GemmCtx& cx, uint32_t sbase,
                                           const float* A, int lda, int m0,
                                           const float* B, int ldb, int n0,
                                           int tid, int lane, int wid)
{
    cx.sbase = sbase;
    const int wm = (wid & 3) * 32;
    const int wn = (wid >> 2) * 32;

    const int arow = tid >> 3, cu = tid & 7;
    cx.aoffs = ((uint32_t)arow * 128u + (uint32_t)cu * 16u)
               ^ (((uint32_t)(arow & 7)) << 4);
    cx.gA = A + (long long)(m0 + arow) * lda + cu * 4;
    cx.gB = B + (long long)(n0 + arow) * ldb + cu * 4;
    cx.a32 = (long long)32 * lda;
    cx.b32 = (long long)32 * ldb;

    const int fr = lane & 15;
    cx.hb = (uint32_t)(lane >> 4) * 16u;
#pragma unroll
    for (int mf = 0; mf < 2; mf++) {
        int row = wm + 16 * mf + fr;
        cx.aSw[mf] = (uint32_t)row * 128u ^ (((uint32_t)(row & 7)) << 4);
    }
#pragma unroll
    for (int g = 0; g < 2; g++) {
        int row = wn + 16 * g + fr;
        cx.bSw[g] = 16384u + ((uint32_t)row * 128u ^ (((uint32_t)(row & 7)) << 4));
    }
}

__device__ __forceinline__ void gemm_issue(const GemmCtx& cx, int sidx, int k0)
{
    const uint32_t sb_ = cx.sbase + (uint32_t)sidx * STAGE_BYTES;
    CPA16(sb_ + cx.aoffs,          cx.gA + k0);
    CPA16(sb_ + cx.aoffs +  4096u, cx.gA + k0 + cx.a32);
    CPA16(sb_ + cx.aoffs +  8192u, cx.gA + k0 + 2 * cx.a32);
    CPA16(sb_ + cx.aoffs + 12288u, cx.gA + k0 + 3 * cx.a32);
    CPA16(sb_ + 16384u + cx.aoffs,         cx.gB + k0);
    CPA16(sb_ + 16384u + cx.aoffs + 4096u, cx.gB + k0 + cx.b32);
}

__device__ __forceinline__ void gemm_mainloop(const GemmCtx& cx, int KB,
                                              float acc[2][4][4])
{
#pragma unroll
    for (int s = 0; s < STAGES - 1; s++) {
        if (s < KB) gemm_issue(cx, s, s * TK);
        CPA_COMMIT();
    }

    int sidx_c = 0;
    int sidx_w = STAGES - 1;
    for (int kb = 0; kb < KB; kb++) {
        CPA_WAIT1();
        __syncthreads();

        const uint32_t buf = cx.sbase + (uint32_t)sidx_c * STAGE_BYTES;
        if (++sidx_c == STAGES) sidx_c = 0;

#pragma unroll
        for (int kblk = 0; kblk < 4; kblk++) {            // 4 x k8 per k-block
            const uint32_t kc = (uint32_t)(kblk * 32) + cx.hb;
            uint32_t a[2][4], b[2][4];
            LDSM4(a[0], buf + (cx.aSw[0] ^ kc));
            LDSM4(a[1], buf + (cx.aSw[1] ^ kc));
            LDSM4(b[0], buf + (cx.bSw[0] ^ kc));
            LDSM4(b[1], buf + (cx.bSw[1] ^ kc));
#pragma unroll
            for (int mf = 0; mf < 2; mf++)
#pragma unroll
                for (int g = 0; g < 2; g++)
#pragma unroll
                    for (int s = 0; s < 2; s++)
                        MMATF32(acc[mf][2 * g + s], a[mf], b[g][s], b[g][s + 2]);

            if (kblk == 0) {
                if (kb + STAGES - 1 < KB)
                    gemm_issue(cx, sidx_w, (kb + STAGES - 1) * TK);
                CPA_COMMIT();
                if (++sidx_w == STAGES) sidx_w = 0;
            }
        }
    }
}

// ---------------------------------------------------------------------------
// Scores kernel: P[q,k] = tf32r(exp(scale * sum_d Q[q,d]K[k,d])) for k<=q,
// 0 for masked elements of live tiles. Also writes deterministic per-
// (row, tile, n-warp) partial sums of the ROUNDED values into PS slots
// [row][bx*2 + nwarp]. Tiles fully above the diagonal skipped (slots stay 0
// from static init and are never read beyond the live range... they read as
// 0 in the rowinv reduction, which sums all 64 slots).
// ---------------------------------------------------------------------------
__global__ void __launch_bounds__(NTHREADS, 3)
scores_gemm(const float* __restrict__ Q, const float* __restrict__ K,
            float* __restrict__ P, float* __restrict__ PS, float scale)
{
    const int by = gridDim.y - 1 - blockIdx.y;     // heavy rows first
    const int bx = blockIdx.x;
    const int m0 = by * TM;
    const int n0 = bx * TN;
    if (n0 > m0 + TM - 1) return;

    extern __shared__ char dsm[];
    const uint32_t sbase = (smem_u32(dsm) + 1023u) & ~1023u;

    const long long z = blockIdx.z;
    const float* A = Q + (long long)z * SS * DD;
    const float* B = K + (long long)z * SS * DD;

    const int tid  = threadIdx.x;
    const int lane = tid & 31;
    const int wid  = tid >> 5;

    GemmCtx cx;
    gemm_setup(cx, sbase, A, DD, m0, B, DD, n0, tid, lane, wid);

    float acc[2][4][4];
#pragma unroll
    for (int mf = 0; mf < 2; mf++)
#pragma unroll
        for (int nf = 0; nf < 4; nf++)
#pragma unroll
            for (int j = 0; j < 4; j++) acc[mf][nf][j] = 0.0f;

    gemm_mainloop(cx, DD / TK, acc);

    // ---- exp epilogue ----
    const int wm = (wid & 3) * 32;
    const int wn = (wid >> 2) * 32;
    const int gq = lane >> 2, t = lane & 3;
    float* Pz = P + (long long)z * SS * SS;

    float psum[4] = {0.0f, 0.0f, 0.0f, 0.0f};   // [mf*2 + rowhalf]
#pragma unroll
    for (int mf = 0; mf < 2; mf++) {
        const int r0 = m0 + wm + 16 * mf + gq;
#pragma unroll
        for (int nf = 0; nf < 4; nf++) {
            const int col = n0 + wn + 8 * nf + 2 * t;
            float e00 = (col     <= r0    ) ? __expf(acc[mf][nf][0] * scale) : 0.0f;
            float e01 = (col + 1 <= r0    ) ? __expf(acc[mf][nf][1] * scale) : 0.0f;
            float e10 = (col     <= r0 + 8) ? __expf(acc[mf][nf][2] * scale) : 0.0f;
            float e11 = (col + 1 <= r0 + 8) ? __expf(acc[mf][nf][3] * scale) : 0.0f;
            e00 = __uint_as_float(tf32r(e00));
            e01 = __uint_as_float(tf32r(e01));
            e10 = __uint_as_float(tf32r(e10));
            e11 = __uint_as_float(tf32r(e11));
            float2 o0, o1;
            o0.x = e00; o0.y = e01;
            o1.x = e10; o1.y = e11;
            *reinterpret_cast<float2*>(Pz + (long long)r0 * SS + col)       = o0;
            *reinterpret_cast<float2*>(Pz + (long long)(r0 + 8) * SS + col) = o1;
            psum[mf * 2]     += e00 + e01;
            psum[mf * 2 + 1] += e10 + e11;
        }
    }
    // reduce across the 4 lanes (t = 0..3) sharing each row
#pragma unroll
    for (int off = 1; off <= 2; off <<= 1)
#pragma unroll
        for (int i = 0; i < 4; i++)
            psum[i] += __shfl_xor_sync(0xFFFFFFFFu, psum[i], off);

    if (t == 0) {
        const int slot = bx * 2 + (wid >> 2);
        const size_t rb = (size_t)z * SS;
        const int rbase = m0 + wm + gq;
        PS[(rb + rbase)      * 64 + slot] = psum[0];
        PS[(rb + rbase + 8)  * 64 + slot] = psum[1];
        PS[(rb + rbase + 16) * 64 + slot] = psum[2];
        PS[(rb + rbase + 24) * 64 + slot] = psum[3];
    }
}

// ---------------------------------------------------------------------------
// Row-sum inversion: RI[row] = 1 / sum(PS[row][0..63]). Dead slots are 0.
// ---------------------------------------------------------------------------
__global__ void __launch_bounds__(256)
rowinv_k(const float* __restrict__ PS, float* __restrict__ RI)
{
    const int i = blockIdx.x * 256 + threadIdx.x;
    if (i >= BB * SS) return;
    const float4* p = reinterpret_cast<const float4*>(PS + (size_t)i * 64);
    float s = 0.0f;
#pragma unroll
    for (int j = 0; j < 16; j++) {
        float4 v = p[j];
        s += (v.x + v.y) + (v.z + v.w);
    }
    RI[i] = 1.0f / s;
}

// ---------------------------------------------------------------------------
// P@V kernel: out[q,d] = RI[q] * sum_k P[q,k] * Vt[d,k]; K limit per q-tile.
// ---------------------------------------------------------------------------
__global__ void __launch_bounds__(NTHREADS, 3)
pv_gemm(const float* __restrict__ P, const float* __restrict__ Vt,
        const float* __restrict__ RI, float* __restrict__ Out)
{
    const int by = gridDim.y - 1 - blockIdx.y;     // heavy rows first
    const int m0 = by * TM;
    const int n0 = blockIdx.x * TN;

    extern __shared__ char dsm[];
    const uint32_t sbase = (smem_u32(dsm) + 1023u) & ~1023u;

    const long long z = blockIdx.z;
    const float* A = P  + (long long)z * SS * SS;
    const float* B = Vt + (long long)z * SS * DD;

    const int KB = ((by + 1) * TM) / TK;

    const int tid  = threadIdx.x;
    const int lane = tid & 31;
    const int wid  = tid >> 5;

    GemmCtx cx;
    gemm_setup(cx, sbase, A, SS, m0, B, SS, n0, tid, lane, wid);

    float acc[2][4][4];
#pragma unroll
    for (int mf = 0; mf < 2; mf++)
#pragma unroll
        for (int nf = 0; nf < 4; nf++)
#pragma unroll
            for (int j = 0; j < 4; j++) acc[mf][nf][j] = 0.0f;

    gemm_mainloop(cx, KB, acc);

    // epilogue: scale by 1/rowsum
    const int wm = (wid & 3) * 32;
    const int wn = (wid >> 2) * 32;
    const int gq = lane >> 2, t = lane & 3;
    float* C = Out + (long long)z * SS * DD;
    const float* RIz = RI + (long long)z * SS;
#pragma unroll
    for (int mf = 0; mf < 2; mf++) {
        const int r0 = m0 + wm + 16 * mf + gq;
        const float inv0 = RIz[r0];
        const float inv1 = RIz[r0 + 8];
#pragma unroll
        for (int nf = 0; nf < 4; nf++) {
            const int col = n0 + wn + 8 * nf + 2 * t;
            float2 o0, o1;
            o0.x = acc[mf][nf][0] * inv0;
            o0.y = acc[mf][nf][1] * inv0;
            o1.x = acc[mf][nf][2] * inv1;
            o1.y = acc[mf][nf][3] * inv1;
            *reinterpret_cast<float2*>(C + (long long)r0 * DD + col)       = o0;
            *reinterpret_cast<float2*>(C + (long long)(r0 + 8) * DD + col) = o1;
        }
    }
}

// ---------------------------------------------------------------------------
// Fused QKV kernel: blockIdx.z in 0..2 selects {Wq,Wk,Wv}.
//   z=0/1: Q/K written tf32-rounded, row-major.
//   z=2  : V written directly transposed (per-batch [DD][SS]) + tf32-rounded.
// ---------------------------------------------------------------------------
__global__ void __launch_bounds__(NTHREADS, 3)
qkv_gemm(const float* __restrict__ X, const float* __restrict__ Wt,
         float* __restrict__ Qo, float* __restrict__ Ko, float* __restrict__ VtO)
{
    const int m0 = blockIdx.y * TM;
    const int n0 = blockIdx.x * TN;
    const int z  = blockIdx.z;

    extern __shared__ char dsm[];
    const uint32_t sbase = (smem_u32(dsm) + 1023u) & ~1023u;

    const float* B = Wt + (size_t)z * DD * DD;

    const int tid  = threadIdx.x;
    const int lane = tid & 31;
    const int wid  = tid >> 5;

    GemmCtx cx;
    gemm_setup(cx, sbase, X, DD, m0, B, DD, n0, tid, lane, wid);

    float acc[2][4][4];
#pragma unroll
    for (int mf = 0; mf < 2; mf++)
#pragma unroll
        for (int nf = 0; nf < 4; nf++)
#pragma unroll
            for (int j = 0; j < 4; j++) acc[mf][nf][j] = 0.0f;

    gemm_mainloop(cx, DD / TK, acc);

    const int wm = (wid & 3) * 32;
    const int wn = (wid >> 2) * 32;
    const int gq = lane >> 2, t = lane & 3;

    if (z < 2) {
        float* C = (z == 0) ? Qo : Ko;
#pragma unroll
        for (int mf = 0; mf < 2; mf++) {
#pragma unroll
            for (int nf = 0; nf < 4; nf++) {
                const int r0  = m0 + wm + 16 * mf + gq;
                const int col = n0 + wn + 8 * nf + 2 * t;
                float2 o0, o1;
                o0.x = __uint_as_float(tf32r(acc[mf][nf][0]));
                o0.y = __uint_as_float(tf32r(acc[mf][nf][1]));
                o1.x = __uint_as_float(tf32r(acc[mf][nf][2]));
                o1.y = __uint_as_float(tf32r(acc[mf][nf][3]));
                *reinterpret_cast<float2*>(C + (long long)r0 * DD + col)       = o0;
                *reinterpret_cast<float2*>(C + (long long)(r0 + 8) * DD + col) = o1;
            }
        }
    } else {
        // ---- transposed V epilogue ----
        __syncthreads();                       // pipeline smem now free
        float* ts = reinterpret_cast<float*>(dsm +
                        (size_t)(sbase - smem_u32(dsm)));   // aligned base
#pragma unroll
        for (int mf = 0; mf < 2; mf++) {
#pragma unroll
            for (int nf = 0; nf < 4; nf++) {
                const int m_ = wm + 16 * mf + gq;
                const int n_ = wn + 8 * nf + 2 * t;
                ts[n_ * 132 + m_]             = acc[mf][nf][0];
                ts[(n_ + 1) * 132 + m_]       = acc[mf][nf][1];
                ts[n_ * 132 + m_ + 8]         = acc[mf][nf][2];
                ts[(n_ + 1) * 132 + m_ + 8]   = acc[mf][nf][3];
            }
        }
        __syncthreads();
        const int vr = tid >> 2;
        const int vc = tid & 3;
        const int b  = m0 >> 11;               // batch (S = 2048)
        const int s0 = m0 & (SS - 1);
        float* dst = VtO + (size_t)b * SS * DD
                   + (size_t)(n0 + vr) * SS + s0 + vc * 32;
#pragma unroll
        for (int i = 0; i < 8; i++) {
            float4 v = *reinterpret_cast<const float4*>(
                ts + vr * 132 + vc * 32 + i * 4);
            v.x = __uint_as_float(tf32r(v.x));
            v.y = __uint_as_float(tf32r(v.y));
            v.z = __uint_as_float(tf32r(v.z));
            v.w = __uint_as_float(tf32r(v.w));
            *reinterpret_cast<float4*>(dst + i * 4) = v;
        }
    }
}

// ---------------------------------------------------------------------------
// fp32 -> tf32-rounded fp32 elementwise (vectorized x4)
// ---------------------------------------------------------------------------
__global__ void __launch_bounds__(256)
convert_tf32(const float* __restrict__ in, float* __restrict__ out, int n4)
{
    int i = blockIdx.x * 256 + threadIdx.x;
    if (i >= n4) return;
    float4 v = reinterpret_cast<const float4*>(in)[i];
    v.x = __uint_as_float(tf32r(v.x));
    v.y = __uint_as_float(tf32r(v.y));
    v.z = __uint_as_float(tf32r(v.z));
    v.w = __uint_as_float(tf32r(v.w));
    reinterpret_cast<float4*>(out)[i] = v;
}

// ---------------------------------------------------------------------------
// Merged W^T transpose: one launch, blockIdx.z in 0..2 selects Wq/Wk/Wv.
// ---------------------------------------------------------------------------
__global__ void __launch_bounds__(256)
transpose_w3(const float* __restrict__ Wq, const float* __restrict__ Wk,
             const float* __restrict__ Wv, float* __restrict__ WtBase)
{
    __shared__ float t[32][33];
    const int z = blockIdx.z;
    const float* in = (z == 0) ? Wq : (z == 1) ? Wk : Wv;
    float* out = WtBase + (size_t)z * DD * DD;
    const int c0 = blockIdx.x * 32, r0 = blockIdx.y * 32;
#pragma unroll
    for (int j = threadIdx.y; j < 32; j += 8)
        t[j][threadIdx.x] = in[(long long)(r0 + j) * DD + c0 + threadIdx.x];
    __syncthreads();
#pragma unroll
    for (int j = threadIdx.y; j < 32; j += 8)
        out[(long long)(c0 + j) * DD + r0 + threadIdx.x] =
            __uint_as_float(tf32r(t[threadIdx.x][j]));
}

// ---------------------------------------------------------------------------
// Launch sequence (graph-capturable: kernel launches only).
// convert(0), W^T(1), QKV+Vt(2), scores+exp(3), rowinv(4), P@V(5).
// ---------------------------------------------------------------------------
extern "C" void kernel_launch(void* const* d_in, const int* in_sizes, int n_in,
                              void* d_out, int out_size)
{
    const float* x  = (const float*)d_in[0];
    const float* Wq = (const float*)d_in[1];
    const float* Wk = (const float*)d_in[2];
    const float* Wv = (const float*)d_in[3];
    float* out = (float*)d_out;

    float *X, *Wt, *Q, *K, *Vt, *P, *PS, *RI;
    cudaGetSymbolAddress((void**)&X,  g_X);
    cudaGetSymbolAddress((void**)&Wt, g_Wt);
    cudaGetSymbolAddress((void**)&Q,  g_Q);
    cudaGetSymbolAddress((void**)&K,  g_K);
    cudaGetSymbolAddress((void**)&Vt, g_Vt);
    cudaGetSymbolAddress((void**)&P,  g_P);
    cudaGetSymbolAddress((void**)&PS, g_PS);
    cudaGetSymbolAddress((void**)&RI, g_RI);

    cudaFuncSetAttribute(qkv_gemm,
                         cudaFuncAttributeMaxDynamicSharedMemorySize, DSM_BYTES);
    cudaFuncSetAttribute(scores_gemm,
                         cudaFuncAttributeMaxDynamicSharedMemorySize, DSM_BYTES);
    cudaFuncSetAttribute(pv_gemm,
                         cudaFuncAttributeMaxDynamicSharedMemorySize, DSM_BYTES);

    const float scale = 0.03125f;     // 1024^-0.5

    dim3 tb(32, 8);

    // idx 0) round x to tf32
    const int xn4 = BB * SS * DD / 4;
    convert_tf32<<<(xn4 + 255) / 256, 256>>>(x, X, xn4);

    // idx 1) W^T merged (K-major, tf32)
    transpose_w3<<<dim3(DD / 32, DD / 32, 3), tb>>>(Wq, Wk, Wv, Wt);

    // idx 2) Fused QKV projection; V emitted transposed (per-batch [DD][SS])
    dim3 gq(DD / TN, (BB * SS) / TM, 3);
    qkv_gemm<<<gq, NTHREADS, DSM_BYTES>>>(X, Wt, Q, K, Vt);

    // idx 3) P = exp(scale * Q K^T), masked; partial row sums to PS
    dim3 gs(SS / TN, SS / TM, BB);
    scores_gemm<<<gs, NTHREADS, DSM_BYTES>>>(Q, K, P, PS, scale);

    // idx 4) RI = 1 / row sums
    rowinv_k<<<(BB * SS + 255) / 256, 256>>>(PS, RI);

    // idx 5) out = RI * (P @ V)
    dim3 gp(DD / TN, SS / TM, BB);
    pv_gemm<<<gp, NTHREADS, DSM_BYTES>>>(P, Vt, RI, out);
}

// round 14
// speedup vs baseline: 1.1211x; 1.0028x over previous
#include <cuda_runtime.h>
#include <cstdint>
#include <math.h>

#define BB 4
#define SS 2048
#define DD 1024

#define TM 128
#define TN 64
#define TK 32
#define NTHREADS 256
#define STAGES 3
#define STAGE_BYTES 24576            // A fp32 16K | B fp32 8K
#define DSM_BYTES (STAGES * STAGE_BYTES + 1024)

// live score tiles per batch: sum_{by=0}^{15} 2(by+1) = 272
#define LIVE_TILES 272

// ---------------------------------------------------------------------------
// Scratch (__device__ globals; zero-initialized at module load — PS relies on
// this: slots of masked tiles are never written and read as 0).
// ---------------------------------------------------------------------------
__device__ float g_X [(size_t)BB * SS * DD];          // x (tf32)      32 MB
__device__ float g_Wt[3][(size_t)DD * DD];            // W^T (tf32)    12 MB
__device__ float g_Q [(size_t)BB * SS * DD];          // Q (tf32)      32 MB
__device__ float g_K [(size_t)BB * SS * DD];          // K (tf32)      32 MB
__device__ float g_Vt[(size_t)BB * SS * DD];          // V^T (tf32)    32 MB
__device__ float g_P [(size_t)BB * SS * SS];          // exp-scores     64 MB
__device__ float g_PS[(size_t)BB * SS * 64];          // row partials    2 MB

// ---------------------------------------------------------------------------
// Helpers
// ---------------------------------------------------------------------------
__device__ __forceinline__ uint32_t smem_u32(const void* p) {
    uint32_t a;
    asm("{ .reg .u64 t; cvta.to.shared.u64 t, %1; cvt.u32.u64 %0, t; }"
        : "=r"(a) : "l"(p));
    return a;
}

__device__ __forceinline__ uint32_t tf32r(float f) {
    uint32_t r;
    asm("cvt.rna.tf32.f32 %0, %1;" : "=r"(r) : "f"(f));
    return r;
}

#define LDSM4(r, a)                                                        \
    asm volatile("ldmatrix.sync.aligned.m8n8.x4.shared.b16 "               \
                 "{%0,%1,%2,%3}, [%4];"                                    \
                 : "=r"((r)[0]), "=r"((r)[1]), "=r"((r)[2]), "=r"((r)[3])  \
                 : "r"(a))

#define MMATF32(d, a, b0, b1)                                              \
    asm volatile("mma.sync.aligned.m16n8k8.row.col.f32.tf32.tf32.f32 "     \
                 "{%0,%1,%2,%3},{%4,%5,%6,%7},{%8,%9},{%0,%1,%2,%3};"      \
                 : "+f"((d)[0]), "+f"((d)[1]), "+f"((d)[2]), "+f"((d)[3])  \
                 : "r"((a)[0]), "r"((a)[1]), "r"((a)[2]), "r"((a)[3]),     \
                   "r"(b0), "r"(b1))

#define CPA16(dst, src)                                                    \
    asm volatile("cp.async.cg.shared.global [%0], [%1], 16;"               \
                 :: "r"(dst), "l"(src))
#define CPA_COMMIT()  asm volatile("cp.async.commit_group;" ::: "memory")
#define CPA_WAIT1()   asm volatile("cp.async.wait_group 1;" ::: "memory")

// ===========================================================================
// Shared GEMM body (CTA 128x64, 3-stage cp.async, warp tile 32x32).
// ===========================================================================
struct GemmCtx {
    uint32_t sbase;
    uint32_t aoffs;
    const float* gA;
    const float* gB;
    long long a32, b32;
    uint32_t aSw[2], bSw[2];
    uint32_t hb;
};

__device__ __forceinline__ void gemm_setup(GemmCtx& cx, uint32_t sbase,
                                           const float* A, int lda, int m0,
                                           const float* B, int ldb, int n0,
                                           int tid, int lane, int wid)
{
    cx.sbase = sbase;
    const int wm = (wid & 3) * 32;
    const int wn = (wid >> 2) * 32;

    const int arow = tid >> 3, cu = tid & 7;
    cx.aoffs = ((uint32_t)arow * 128u + (uint32_t)cu * 16u)
               ^ (((uint32_t)(arow & 7)) << 4);
    cx.gA = A + (long long)(m0 + arow) * lda + cu * 4;
    cx.gB = B + (long long)(n0 + arow) * ldb + cu * 4;
    cx.a32 = (long long)32 * lda;
    cx.b32 = (long long)32 * ldb;

    const int fr = lane & 15;
    cx.hb = (uint32_t)(lane >> 4) * 16u;
#pragma unroll
    for (int mf = 0; mf < 2; mf++) {
        int row = wm + 16 * mf + fr;
        cx.aSw[mf] = (uint32_t)row * 128u ^ (((uint32_t)(row & 7)) << 4);
    }
#pragma unroll
    for (int g = 0; g < 2; g++) {
        int row = wn + 16 * g + fr;
        cx.bSw[g] = 16384u + ((uint32_t)row * 128u ^ (((uint32_t)(row & 7)) << 4));
    }
}

__device__ __forceinline__ void gemm_issue(const GemmCtx& cx, int sidx, int k0)
{
    const uint32_t sb_ = cx.sbase + (uint32_t)sidx * STAGE_BYTES;
    CPA16(sb_ + cx.aoffs,          cx.gA + k0);
    CPA16(sb_ + cx.aoffs +  4096u, cx.gA + k0 + cx.a32);
    CPA16(sb_ + cx.aoffs +  8192u, cx.gA + k0 + 2 * cx.a32);
    CPA16(sb_ + cx.aoffs + 12288u, cx.gA + k0 + 3 * cx.a32);
    CPA16(sb_ + 16384u + cx.aoffs,         cx.gB + k0);
    CPA16(sb_ + 16384u + cx.aoffs + 4096u, cx.gB + k0 + cx.b32);
}

__device__ __forceinline__ void gemm_mainloop(const GemmCtx& cx, int KB,
                                              float acc[2][4][4])
{
#pragma unroll
    for (int s = 0; s < STAGES - 1; s++) {
        if (s < KB) gemm_issue(cx, s, s * TK);
        CPA_COMMIT();
    }

    int sidx_c = 0;
    int sidx_w = STAGES - 1;
    for (int kb = 0; kb < KB; kb++) {
        CPA_WAIT1();
        __syncthreads();

        const uint32_t buf = cx.sbase + (uint32_t)sidx_c * STAGE_BYTES;
        if (++sidx_c == STAGES) sidx_c = 0;

#pragma unroll
        for (int kblk = 0; kblk < 4; kblk++) {            // 4 x k8 per k-block
            const uint32_t kc = (uint32_t)(kblk * 32) + cx.hb;
            uint32_t a[2][4], b[2][4];
            LDSM4(a[0], buf + (cx.aSw[0] ^ kc));
            LDSM4(a[1], buf + (cx.aSw[1] ^ kc));
            LDSM4(b[0], buf + (cx.bSw[0] ^ kc));
            LDSM4(b[1], buf + (cx.bSw[1] ^ kc));
#pragma unroll
            for (int mf = 0; mf < 2; mf++)
#pragma unroll
                for (int g = 0; g < 2; g++)
#pragma unroll
                    for (int s = 0; s < 2; s++)
                        MMATF32(acc[mf][2 * g + s], a[mf], b[g][s], b[g][s + 2]);

            if (kblk == 0) {
                if (kb + STAGES - 1 < KB)
                    gemm_issue(cx, sidx_w, (kb + STAGES - 1) * TK);
                CPA_COMMIT();
                if (++sidx_w == STAGES) sidx_w = 0;
            }
        }
    }
}

// ---------------------------------------------------------------------------
// Scores kernel, COMPACT triangular grid: grid.x = LIVE_TILES (per batch),
// decoded to (by, bx) with heavy q-tile rows scheduled first.
// P[q,k] = tf32r(exp(scale * QK^T)) for k<=q, 0 for masked elems of live
// tiles. Deterministic per-(row, tile, n-warp) partial sums -> PS.
// ---------------------------------------------------------------------------
__global__ void __launch_bounds__(NTHREADS, 3)
scores_gemm(const float* __restrict__ Q, const float* __restrict__ K,
            float* __restrict__ P, float* __restrict__ PS, float scale)
{
    // triangular decode, heavy rows first
    const int t = LIVE_TILES - 1 - blockIdx.x;           // 0..271
    int by = (int)((sqrtf(4.0f * t + 1.0f) - 1.0f) * 0.5f);
    if ((by + 1) * (by + 2) <= t) by++;
    if (by * (by + 1) > t) by--;
    const int bx = t - by * (by + 1);                    // 0..2(by+1)-1

    const int m0 = by * TM;
    const int n0 = bx * TN;

    extern __shared__ char dsm[];
    const uint32_t sbase = (smem_u32(dsm) + 1023u) & ~1023u;

    const long long z = blockIdx.z;
    const float* A = Q + (long long)z * SS * DD;
    const float* B = K + (long long)z * SS * DD;

    const int tid  = threadIdx.x;
    const int lane = tid & 31;
    const int wid  = tid >> 5;

    GemmCtx cx;
    gemm_setup(cx, sbase, A, DD, m0, B, DD, n0, tid, lane, wid);

    float acc[2][4][4];
#pragma unroll
    for (int mf = 0; mf < 2; mf++)
#pragma unroll
        for (int nf = 0; nf < 4; nf++)
#pragma unroll
            for (int j = 0; j < 4; j++) acc[mf][nf][j] = 0.0f;

    gemm_mainloop(cx, DD / TK, acc);

    // ---- exp epilogue ----
    const int wm = (wid & 3) * 32;
    const int wn = (wid >> 2) * 32;
    const int gq = lane >> 2, tt = lane & 3;
    float* Pz = P + (long long)z * SS * SS;

    float psum[4] = {0.0f, 0.0f, 0.0f, 0.0f};   // [mf*2 + rowhalf]
#pragma unroll
    for (int mf = 0; mf < 2; mf++) {
        const int r0 = m0 + wm + 16 * mf + gq;
#pragma unroll
        for (int nf = 0; nf < 4; nf++) {
            const int col = n0 + wn + 8 * nf + 2 * tt;
            float e00 = (col     <= r0    ) ? __expf(acc[mf][nf][0] * scale) : 0.0f;
            float e01 = (col + 1 <= r0    ) ? __expf(acc[mf][nf][1] * scale) : 0.0f;
            float e10 = (col     <= r0 + 8) ? __expf(acc[mf][nf][2] * scale) : 0.0f;
            float e11 = (col + 1 <= r0 + 8) ? __expf(acc[mf][nf][3] * scale) : 0.0f;
            e00 = __uint_as_float(tf32r(e00));
            e01 = __uint_as_float(tf32r(e01));
            e10 = __uint_as_float(tf32r(e10));
            e11 = __uint_as_float(tf32r(e11));
            float2 o0, o1;
            o0.x = e00; o0.y = e01;
            o1.x = e10; o1.y = e11;
            *reinterpret_cast<float2*>(Pz + (long long)r0 * SS + col)       = o0;
            *reinterpret_cast<float2*>(Pz + (long long)(r0 + 8) * SS + col) = o1;
            psum[mf * 2]     += e00 + e01;
            psum[mf * 2 + 1] += e10 + e11;
        }
    }
#pragma unroll
    for (int off = 1; off <= 2; off <<= 1)
#pragma unroll
        for (int i = 0; i < 4; i++)
            psum[i] += __shfl_xor_sync(0xFFFFFFFFu, psum[i], off);

    if (tt == 0) {
        const int slot = bx * 2 + (wid >> 2);
        const size_t rb = (size_t)z * SS;
        const int rbase = m0 + wm + gq;
        PS[(rb + rbase)      * 64 + slot] = psum[0];
        PS[(rb + rbase + 8)  * 64 + slot] = psum[1];
        PS[(rb + rbase + 16) * 64 + slot] = psum[2];
        PS[(rb + rbase + 24) * 64 + slot] = psum[3];
    }
}

// ---------------------------------------------------------------------------
// P@V kernel: out[q,d] = (1/rowsum(q)) * sum_k P[q,k]*Vt[d,k]; per-q K limit.
// Row-sum inverses computed in the prologue from PS (same summation order as
// the old rowinv kernel -> bit-identical); no separate rowinv launch.
// ---------------------------------------------------------------------------
__global__ void __launch_bounds__(NTHREADS, 3)
pv_gemm(const float* __restrict__ P, const float* __restrict__ Vt,
        const float* __restrict__ PS, float* __restrict__ Out)
{
    const int by = gridDim.y - 1 - blockIdx.y;     // heavy rows first
    const int m0 = by * TM;
    const int n0 = blockIdx.x * TN;

    extern __shared__ char dsm[];
    const uint32_t sbase = (smem_u32(dsm) + 1023u) & ~1023u;

    const long long z = blockIdx.z;
    const float* A = P  + (long long)z * SS * SS;
    const float* B = Vt + (long long)z * SS * DD;

    const int KB = ((by + 1) * TM) / TK;

    const int tid  = threadIdx.x;
    const int lane = tid & 31;
    const int wid  = tid >> 5;

    // ---- per-thread row-sum inverses for this thread's 4 output rows ----
    const int wm = (wid & 3) * 32;
    const int gq = lane >> 2, tt = lane & 3;
    float inv[4];
    {
        const size_t rb = (size_t)z * SS;
        const int rbase = m0 + wm + gq;
#pragma unroll
        for (int r = 0; r < 4; r++) {
            const float4* ps = reinterpret_cast<const float4*>(
                PS + (rb + rbase + 8 * r) * 64);
            float s = 0.0f;
#pragma unroll
            for (int j = 0; j < 16; j++) {
                float4 v = ps[j];
                s += (v.x + v.y) + (v.z + v.w);
            }
            inv[r] = 1.0f / s;
        }
    }

    GemmCtx cx;
    gemm_setup(cx, sbase, A, SS, m0, B, SS, n0, tid, lane, wid);

    float acc[2][4][4];
#pragma unroll
    for (int mf = 0; mf < 2; mf++)
#pragma unroll
        for (int nf = 0; nf < 4; nf++)
#pragma unroll
            for (int j = 0; j < 4; j++) acc[mf][nf][j] = 0.0f;

    gemm_mainloop(cx, KB, acc);

    // epilogue: scale by 1/rowsum
    const int wn = (wid >> 2) * 32;
    float* C = Out + (long long)z * SS * DD;
#pragma unroll
    for (int mf = 0; mf < 2; mf++) {
        const int r0 = m0 + wm + 16 * mf + gq;
        const float inv0 = inv[mf * 2];
        const float inv1 = inv[mf * 2 + 1];
#pragma unroll
        for (int nf = 0; nf < 4; nf++) {
            const int col = n0 + wn + 8 * nf + 2 * tt;
            float2 o0, o1;
            o0.x = acc[mf][nf][0] * inv0;
            o0.y = acc[mf][nf][1] * inv0;
            o1.x = acc[mf][nf][2] * inv1;
            o1.y = acc[mf][nf][3] * inv1;
            *reinterpret_cast<float2*>(C + (long long)r0 * DD + col)       = o0;
            *reinterpret_cast<float2*>(C + (long long)(r0 + 8) * DD + col) = o1;
        }
    }
}

// ---------------------------------------------------------------------------
// Fused QKV kernel: blockIdx.z in 0..2 selects {Wq,Wk,Wv}.
//   z=0/1: Q/K written tf32-rounded, row-major.
//   z=2  : V written directly transposed (per-batch [DD][SS]) + tf32-rounded.
// ---------------------------------------------------------------------------
__global__ void __launch_bounds__(NTHREADS, 3)
qkv_gemm(const float* __restrict__ X, const float* __restrict__ Wt,
         float* __restrict__ Qo, float* __restrict__ Ko, float* __restrict__ VtO)
{
    const int m0 = blockIdx.y * TM;
    const int n0 = blockIdx.x * TN;
    const int z  = blockIdx.z;

    extern __shared__ char dsm[];
    const uint32_t sbase = (smem_u32(dsm) + 1023u) & ~1023u;

    const float* B = Wt + (size_t)z * DD * DD;

    const int tid  = threadIdx.x;
    const int lane = tid & 31;
    const int wid  = tid >> 5;

    GemmCtx cx;
    gemm_setup(cx, sbase, X, DD, m0, B, DD, n0, tid, lane, wid);

    float acc[2][4][4];
#pragma unroll
    for (int mf = 0; mf < 2; mf++)
#pragma unroll
        for (int nf = 0; nf < 4; nf++)
#pragma unroll
            for (int j = 0; j < 4; j++) acc[mf][nf][j] = 0.0f;

    gemm_mainloop(cx, DD / TK, acc);

    const int wm = (wid & 3) * 32;
    const int wn = (wid >> 2) * 32;
    const int gq = lane >> 2, t = lane & 3;

    if (z < 2) {
        float* C = (z == 0) ? Qo : Ko;
#pragma unroll
        for (int mf = 0; mf < 2; mf++) {
#pragma unroll
            for (int nf = 0; nf < 4; nf++) {
                const int r0  = m0 + wm + 16 * mf + gq;
                const int col = n0 + wn + 8 * nf + 2 * t;
                float2 o0, o1;
                o0.x = __uint_as_float(tf32r(acc[mf][nf][0]));
                o0.y = __uint_as_float(tf32r(acc[mf][nf][1]));
                o1.x = __uint_as_float(tf32r(acc[mf][nf][2]));
                o1.y = __uint_as_float(tf32r(acc[mf][nf][3]));
                *reinterpret_cast<float2*>(C + (long long)r0 * DD + col)       = o0;
                *reinterpret_cast<float2*>(C + (long long)(r0 + 8) * DD + col) = o1;
            }
        }
    } else {
        // ---- transposed V epilogue ----
        __syncthreads();                       // pipeline smem now free
        float* ts = reinterpret_cast<float*>(dsm +
                        (size_t)(sbase - smem_u32(dsm)));   // aligned base
#pragma unroll
        for (int mf = 0; mf < 2; mf++) {
#pragma unroll
            for (int nf = 0; nf < 4; nf++) {
                const int m_ = wm + 16 * mf + gq;
                const int n_ = wn + 8 * nf + 2 * t;
                ts[n_ * 132 + m_]             = acc[mf][nf][0];
                ts[(n_ + 1) * 132 + m_]       = acc[mf][nf][1];
                ts[n_ * 132 + m_ + 8]         = acc[mf][nf][2];
                ts[(n_ + 1) * 132 + m_ + 8]   = acc[mf][nf][3];
            }
        }
        __syncthreads();
        const int vr = tid >> 2;
        const int vc = tid & 3;
        const int b  = m0 >> 11;               // batch (S = 2048)
        const int s0 = m0 & (SS - 1);
        float* dst = VtO + (size_t)b * SS * DD
                   + (size_t)(n0 + vr) * SS + s0 + vc * 32;
#pragma unroll
        for (int i = 0; i < 8; i++) {
            float4 v = *reinterpret_cast<const float4*>(
                ts + vr * 132 + vc * 32 + i * 4);
            v.x = __uint_as_float(tf32r(v.x));
            v.y = __uint_as_float(tf32r(v.y));
            v.z = __uint_as_float(tf32r(v.z));
            v.w = __uint_as_float(tf32r(v.w));
            *reinterpret_cast<float4*>(dst + i * 4) = v;
        }
    }
}

// ---------------------------------------------------------------------------
// Prep kernel (merged): blocks [0, XN4B) convert x -> tf32; remaining blocks
// transpose Wq/Wk/Wv -> Wt (K-major, tf32).
// ---------------------------------------------------------------------------
#define XN4   (BB * SS * DD / 4)
#define XN4B  ((XN4 + 255) / 256)              // 8192 blocks
#define WTB   (3 * (DD / 32) * (DD / 32))      // 3072 blocks

__global__ void __launch_bounds__(256)
prep_kernel(const float* __restrict__ x, float* __restrict__ X,
            const float* __restrict__ Wq, const float* __restrict__ Wk,
            const float* __restrict__ Wv, float* __restrict__ WtBase)
{
    __shared__ float t[32][33];
    const int b = blockIdx.x;
    const int tid = threadIdx.x;

    if (b < XN4B) {
        const int i = b * 256 + tid;
        if (i >= XN4) return;
        float4 v = reinterpret_cast<const float4*>(x)[i];
        v.x = __uint_as_float(tf32r(v.x));
        v.y = __uint_as_float(tf32r(v.y));
        v.z = __uint_as_float(tf32r(v.z));
        v.w = __uint_as_float(tf32r(v.w));
        reinterpret_cast<float4*>(X)[i] = v;
    } else {
        const int idx = b - XN4B;
        const int z   = idx >> 10;                  // /1024
        const int rem = idx & 1023;
        const int bx  = rem & 31;
        const int byy = rem >> 5;
        const float* in = (z == 0) ? Wq : (z == 1) ? Wk : Wv;
        float* out = WtBase + (size_t)z * DD * DD;
        const int c0 = bx * 32, r0 = byy * 32;
        const int tx = tid & 31, ty = tid >> 5;     // (32, 8)
#pragma unroll
        for (int j = ty; j < 32; j += 8)
            t[j][tx] = in[(long long)(r0 + j) * DD + c0 + tx];
        __syncthreads();
#pragma unroll
        for (int j = ty; j < 32; j += 8)
            out[(long long)(c0 + j) * DD + r0 + tx] =
                __uint_as_float(tf32r(t[tx][j]));
    }
}

// ---------------------------------------------------------------------------
// Launch sequence (graph-capturable: kernel launches only).
// prep(0), QKV+Vt(1), scores+exp compact(2), P@V+rowinv(3) — 4 nodes.
// ---------------------------------------------------------------------------
extern "C" void kernel_launch(void* const* d_in, const int* in_sizes, int n_in,
                              void* d_out, int out_size)
{
    const float* x  = (const float*)d_in[0];
    const float* Wq = (const float*)d_in[1];
    const float* Wk = (const float*)d_in[2];
    const float* Wv = (const float*)d_in[3];
    float* out = (float*)d_out;

    float *X, *Wt, *Q, *K, *Vt, *P, *PS;
    cudaGetSymbolAddress((void**)&X,  g_X);
    cudaGetSymbolAddress((void**)&Wt, g_Wt);
    cudaGetSymbolAddress((void**)&Q,  g_Q);
    cudaGetSymbolAddress((void**)&K,  g_K);
    cudaGetSymbolAddress((void**)&Vt, g_Vt);
    cudaGetSymbolAddress((void**)&P,  g_P);
    cudaGetSymbolAddress((void**)&PS, g_PS);

    cudaFuncSetAttribute(qkv_gemm,
                         cudaFuncAttributeMaxDynamicSharedMemorySize, DSM_BYTES);
    cudaFuncSetAttribute(scores_gemm,
                         cudaFuncAttributeMaxDynamicSharedMemorySize, DSM_BYTES);
    cudaFuncSetAttribute(pv_gemm,
                         cudaFuncAttributeMaxDynamicSharedMemorySize, DSM_BYTES);

    const float scale = 0.03125f;     // 1024^-0.5

    // idx 0) prep: x -> tf32, W -> W^T (merged)
    prep_kernel<<<XN4B + WTB, 256>>>(x, X, Wq, Wk, Wv, Wt);

    // idx 1) Fused QKV projection; V emitted transposed (per-batch [DD][SS])
    dim3 gq(DD / TN, (BB * SS) / TM, 3);
    qkv_gemm<<<gq, NTHREADS, DSM_BYTES>>>(X, Wt, Q, K, Vt);

    // idx 2) P = exp(scale * Q K^T), masked; partial row sums to PS
    //         compact triangular grid: only live tiles launched
    dim3 gs(LIVE_TILES, 1, BB);
    scores_gemm<<<gs, NTHREADS, DSM_BYTES>>>(Q, K, P, PS, scale);

    // idx 3) out = (1/rowsum) * (P @ V); rowsum inverses from PS in-prologue
    dim3 gp(DD / TN, SS / TM, BB);
    pv_gemm<<<gp, NTHREADS, DSM_BYTES>>>(P, Vt, PS, out);
}